// round 11
// baseline (speedup 1.0000x reference)
#include <cuda_runtime.h>
#include <cuda_bf16.h>
#include <math_constants.h>
#include <cstdint>

#define B_ 2
#define T_ 2048
#define E_ 2048
#define H_ 32
#define D_ 64
#define M_ (B_ * T_)
#define SCALING 0.125f

// ---------------- scratch (__device__ globals; allocation-free rule) --------
__device__ __nv_bfloat16 g_Ahi[M_ * E_];   // split of X; later ctx (attn output)
__device__ __nv_bfloat16 g_Alo[M_ * E_];
__device__ __nv_bfloat16 g_Whi[4][E_ * E_];  // q,k,v,o weight splits
__device__ __nv_bfloat16 g_Wlo[4][E_ * E_];
__device__ __nv_bfloat16 g_Qhi[M_ * E_];
__device__ __nv_bfloat16 g_Qlo[M_ * E_];
__device__ __nv_bfloat16 g_Khi[M_ * E_];
__device__ __nv_bfloat16 g_Klo[M_ * E_];
__device__ __nv_bfloat16 g_Vhi[M_ * E_];
__device__ __nv_bfloat16 g_Vlo[M_ * E_];

// ---------------- helpers ---------------------------------------------------
__device__ __forceinline__ uint32_t smem_u32(const void* p) {
    uint32_t a;
    asm("{ .reg .u64 t; cvta.to.shared.u64 t, %1; cvt.u32.u64 %0, t; }" : "=r"(a) : "l"(p));
    return a;
}
__device__ __forceinline__ void cp16(uint32_t dst, const void* src) {
    asm volatile("cp.async.cg.shared.global [%0], [%1], 16;" :: "r"(dst), "l"(src));
}
__device__ __forceinline__ void cp_commit() {
    asm volatile("cp.async.commit_group;" ::: "memory");
}
template <int N>
__device__ __forceinline__ void cp_wait() {
    asm volatile("cp.async.wait_group %0;" :: "n"(N) : "memory");
}
__device__ __forceinline__ void ldm_x4(uint32_t* d, uint32_t addr) {
    asm volatile("ldmatrix.sync.aligned.m8n8.x4.shared.b16 {%0,%1,%2,%3}, [%4];"
                 : "=r"(d[0]), "=r"(d[1]), "=r"(d[2]), "=r"(d[3]) : "r"(addr));
}
__device__ __forceinline__ void ldm_x4_t(uint32_t* d, uint32_t addr) {
    asm volatile("ldmatrix.sync.aligned.m8n8.x4.trans.shared.b16 {%0,%1,%2,%3}, [%4];"
                 : "=r"(d[0]), "=r"(d[1]), "=r"(d[2]), "=r"(d[3]) : "r"(addr));
}
__device__ __forceinline__ void mma16816(float* c, const uint32_t* a, uint32_t b0, uint32_t b1) {
    asm volatile("mma.sync.aligned.m16n8k16.row.col.f32.bf16.bf16.f32 "
                 "{%0,%1,%2,%3}, {%4,%5,%6,%7}, {%8,%9}, {%0,%1,%2,%3};"
                 : "+f"(c[0]), "+f"(c[1]), "+f"(c[2]), "+f"(c[3])
                 : "r"(a[0]), "r"(a[1]), "r"(a[2]), "r"(a[3]), "r"(b0), "r"(b1));
}
__device__ __forceinline__ uint32_t pack_bf16(float lo, float hi) {
    uint32_t r;
    asm("cvt.rn.bf16x2.f32 %0, %1, %2;" : "=r"(r) : "f"(hi), "f"(lo));
    return r;
}
__device__ __forceinline__ void split2(float a, float b, uint32_t& hw, uint32_t& lw) {
    hw = pack_bf16(a, b);
    float ha = __uint_as_float(hw << 16);
    float hb = __uint_as_float(hw & 0xffff0000u);
    lw = pack_bf16(a - ha, b - hb);
}
// swizzle for 32-col (64B-row) bf16 tiles: 4 chunks of 16B per row
__device__ __forceinline__ uint32_t tile_off(int r, int c) {
    return (uint32_t)(r * 64 + ((c ^ ((r >> 1) & 3)) << 4));
}
// swizzle for 64-col (128B-row) bf16 tiles: 8 chunks of 16B per row
__device__ __forceinline__ uint32_t toff128(int r, int c) {
    return (uint32_t)(r * 128 + ((c ^ (r & 7)) << 4));
}

// ---------------------------------------------------------------------------
// splits
// ---------------------------------------------------------------------------
__global__ __launch_bounds__(256) void split_fp32(
    const float* __restrict__ x, __nv_bfloat16* __restrict__ hi,
    __nv_bfloat16* __restrict__ lo, int n4)
{
    int i = blockIdx.x * 256 + threadIdx.x;
    if (i >= n4) return;
    float4 v = ((const float4*)x)[i];
    uint32_t h0, l0, h1, l1;
    split2(v.x, v.y, h0, l0);
    split2(v.z, v.w, h1, l1);
    ((uint2*)hi)[i] = make_uint2(h0, h1);
    ((uint2*)lo)[i] = make_uint2(l0, l1);
}

struct SplitJobs {
    const float* src[4];
    __nv_bfloat16* hi[4];
    __nv_bfloat16* lo[4];
};
__global__ __launch_bounds__(256) void split_weights(SplitJobs jobs, int n4)
{
    int i = blockIdx.x * 256 + threadIdx.x;
    if (i >= n4) return;
    const int w = blockIdx.y;
    float4 v = ((const float4*)jobs.src[w])[i];
    uint32_t h0, l0, h1, l1;
    split2(v.x, v.y, h0, l0);
    split2(v.z, v.w, h1, l1);
    ((uint2*)jobs.hi[w])[i] = make_uint2(h0, h1);
    ((uint2*)jobs.lo[w])[i] = make_uint2(l0, l1);
}

// ---------------------------------------------------------------------------
// bf16x3 split GEMM: CTA 128x128, warp 32x64, BK=32, 3 stages, 2 CTAs/SM.
// R11: term-major MMA ordering (no 3-chains on one accumulator).
// Stage 32KB: Ahi 8K | Alo 8K | Whi 8K | Wlo 8K
// ---------------------------------------------------------------------------
#define GSTAGE 32768
#define SMEM_GEMM (3 * GSTAGE)
#define NCH32 (E_ / 32)

struct GemmJobs {
    const __nv_bfloat16* Whi[3];
    const __nv_bfloat16* Wlo[3];
    const float* bias[3];
    __nv_bfloat16* Ohi[3];
    __nv_bfloat16* Olo[3];
    float* C[3];
    float alpha[3];
};

__global__ __launch_bounds__(256, 2) void gemm_tc(
    const __nv_bfloat16* __restrict__ Ahi, const __nv_bfloat16* __restrict__ Alo,
    GemmJobs jobs)
{
    extern __shared__ __align__(1024) char smem[];
    const uint32_t su = smem_u32(smem);
    const int tid = threadIdx.x, wid = tid >> 5, lane = tid & 31;
    const int brow = blockIdx.y * 128, bcol = blockIdx.x * 128;
    const int jz = blockIdx.z;
    const __nv_bfloat16* Whi = jobs.Whi[jz];
    const __nv_bfloat16* Wlo = jobs.Wlo[jz];
    const int wm = wid & 3;        // warp row block (32 rows)
    const int wn = wid >> 2;       // warp col block (64 cols)

    float acc[2][8][4];
#pragma unroll
    for (int mt = 0; mt < 2; mt++)
#pragma unroll
        for (int j = 0; j < 8; j++)
#pragma unroll
            for (int q = 0; q < 4; q++) acc[mt][j][q] = 0.f;

    auto load_part = [&](int k0, int s, int p) {
        const uint32_t base = su + s * GSTAGE;
        int idx = tid + p * 256;           // 0..511: 128 rows x 4 chunks
        int r = idx >> 2, c = idx & 3;
        uint32_t off = tile_off(r, c);
        size_t ga = (size_t)(brow + r) * E_ + k0 + c * 8;
        size_t gw = (size_t)(bcol + r) * E_ + k0 + c * 8;
        cp16(base +         off, Ahi + ga);
        cp16(base +  8192 + off, Alo + ga);
        cp16(base + 16384 + off, Whi + gw);
        cp16(base + 24576 + off, Wlo + gw);
    };
    auto load_chunk = [&](int k0, int s) {
#pragma unroll
        for (int p = 0; p < 2; p++) load_part(k0, s, p);
        cp_commit();
    };

    load_chunk(0, 0);
    load_chunk(32, 1);

    for (int k = 0; k < NCH32; k++) {
        if (k + 1 < NCH32) { cp_wait<1>(); } else { cp_wait<0>(); }
        __syncthreads();
        const bool pre = (k + 2 < NCH32);
        const int ps = (k + 2) % 3;
        const int pk = (k + 2) * 32;

        const uint32_t bA_hi = su + (k % 3) * GSTAGE;
        const uint32_t bA_lo = bA_hi + 8192;
        const uint32_t bW_hi = bA_hi + 16384;
        const uint32_t bW_lo = bA_hi + 24576;

#pragma unroll
        for (int ks = 0; ks < 2; ks++) {
            if (pre) load_part(pk, ps, ks);
            const int cc = ks * 2 + (lane >> 4);
            uint32_t ah[2][4], al[2][4];
#pragma unroll
            for (int mt = 0; mt < 2; mt++) {
                const uint32_t off = tile_off(wm * 32 + mt * 16 + (lane & 15), cc);
                ldm_x4(ah[mt], bA_hi + off);
                ldm_x4(al[mt], bA_lo + off);
            }
            uint32_t bh[4][4], bl[4][4];
#pragma unroll
            for (int nb = 0; nb < 4; nb++) {
                const uint32_t off = tile_off(wn * 64 + nb * 16 + (lane & 15), cc);
                ldm_x4(bh[nb], bW_hi + off);
                ldm_x4(bl[nb], bW_lo + off);
            }
            // term-major: 16 independent accumulators between dependent MMAs
#pragma unroll
            for (int mt = 0; mt < 2; mt++)
#pragma unroll
                for (int j = 0; j < 8; j++) {
                    const int nb = j >> 1, sel = j & 1;
                    mma16816(acc[mt][j], ah[mt], bh[nb][sel], bh[nb][sel + 2]);
                }
#pragma unroll
            for (int mt = 0; mt < 2; mt++)
#pragma unroll
                for (int j = 0; j < 8; j++) {
                    const int nb = j >> 1, sel = j & 1;
                    mma16816(acc[mt][j], ah[mt], bl[nb][sel], bl[nb][sel + 2]);
                }
#pragma unroll
            for (int mt = 0; mt < 2; mt++)
#pragma unroll
                for (int j = 0; j < 8; j++) {
                    const int nb = j >> 1, sel = j & 1;
                    mma16816(acc[mt][j], al[mt], bh[nb][sel], bh[nb][sel + 2]);
                }
        }
        if (pre) cp_commit();
    }

    const float alpha = jobs.alpha[jz];
    const float* bias = jobs.bias[jz];
    __nv_bfloat16* Ohi = jobs.Ohi[jz];
    __nv_bfloat16* Olo = jobs.Olo[jz];
    float* C = jobs.C[jz];
#pragma unroll
    for (int mt = 0; mt < 2; mt++) {
        const int r0 = brow + wm * 32 + mt * 16 + (lane >> 2);
#pragma unroll
        for (int j = 0; j < 8; j++) {
            const int col = bcol + wn * 64 + j * 8 + (lane & 3) * 2;
            const float bx = bias[col], by = bias[col + 1];
            float v00 = alpha * (acc[mt][j][0] + bx);
            float v01 = alpha * (acc[mt][j][1] + by);
            float v10 = alpha * (acc[mt][j][2] + bx);
            float v11 = alpha * (acc[mt][j][3] + by);
            if (Ohi) {
                uint32_t hw, lw;
                split2(v00, v01, hw, lw);
                *(uint32_t*)&Ohi[(size_t)r0 * E_ + col] = hw;
                *(uint32_t*)&Olo[(size_t)r0 * E_ + col] = lw;
                split2(v10, v11, hw, lw);
                *(uint32_t*)&Ohi[(size_t)(r0 + 8) * E_ + col] = hw;
                *(uint32_t*)&Olo[(size_t)(r0 + 8) * E_ + col] = lw;
            } else {
                *(float2*)&C[(size_t)r0 * E_ + col]       = make_float2(v00, v01);
                *(float2*)&C[(size_t)(r0 + 8) * E_ + col] = make_float2(v10, v11);
            }
        }
    }
}

// ---------------------------------------------------------------------------
// Tensor-core flash attention. R11: term-major MMA ordering in QK^T and PV.
// ---------------------------------------------------------------------------
#define AT_STAGE 32768
#define SMEM_ATTN (16384 + 2 * AT_STAGE)

__global__ __launch_bounds__(128, 1) void attn_tc(
    const __nv_bfloat16* __restrict__ Qhi, const __nv_bfloat16* __restrict__ Qlo,
    const __nv_bfloat16* __restrict__ Khi, const __nv_bfloat16* __restrict__ Klo,
    const __nv_bfloat16* __restrict__ Vhi, const __nv_bfloat16* __restrict__ Vlo,
    __nv_bfloat16* __restrict__ Chi, __nv_bfloat16* __restrict__ Clo)
{
    extern __shared__ __align__(1024) char smem[];
    const uint32_t su = smem_u32(smem);
    const int tid = threadIdx.x, w = tid >> 5, lane = tid & 31;
    const int qt = gridDim.x - 1 - blockIdx.x;
    const int bh = blockIdx.y;
    const int b = bh >> 5, h = bh & 31;

    const size_t rowQ0 = (size_t)(b * T_ + qt * 64);
    const size_t rowK0 = (size_t)(b * T_);
    const int hoff = h * 64;

    auto load_q = [&]() {
#pragma unroll
        for (int it = 0; it < 4; it++) {
            int idx = tid + it * 128;
            int r = idx >> 3, c = idx & 7;
            uint32_t off = toff128(r, c);
            size_t g = (rowQ0 + r) * E_ + hoff + c * 8;
            cp16(su +        off, Qhi + g);
            cp16(su + 8192 + off, Qlo + g);
        }
    };
    auto load_kv = [&](int jt, int s) {
        const uint32_t base = su + 16384 + s * AT_STAGE;
#pragma unroll
        for (int it = 0; it < 4; it++) {
            int idx = tid + it * 128;
            int r = idx >> 3, c = idx & 7;
            uint32_t off = toff128(r, c);
            size_t g = (rowK0 + jt * 64 + r) * E_ + hoff + c * 8;
            cp16(base +         off, Khi + g);
            cp16(base +  8192 + off, Klo + g);
            cp16(base + 16384 + off, Vhi + g);
            cp16(base + 24576 + off, Vlo + g);
        }
    };

    load_q();
    load_kv(0, 0);
    cp_commit();
    cp_wait<0>();
    __syncthreads();

    uint32_t qh[4][4], ql[4][4];
#pragma unroll
    for (int ks = 0; ks < 4; ks++) {
        const uint32_t off = toff128(16 * w + (lane & 15), ks * 2 + (lane >> 4));
        ldm_x4(qh[ks], su + off);
        ldm_x4(ql[ks], su + 8192 + off);
    }

    float oc[8][4];
#pragma unroll
    for (int nb = 0; nb < 8; nb++)
#pragma unroll
        for (int q = 0; q < 4; q++) oc[nb][q] = 0.f;
    float mrow0 = -CUDART_INF_F, mrow1 = -CUDART_INF_F;
    float lrow0 = 0.f, lrow1 = 0.f;

    for (int jt = 0; jt <= qt; jt++) {
        const int s = jt & 1;
        if (jt + 1 <= qt) {
            load_kv(jt + 1, s ^ 1);
            cp_commit();
            cp_wait<1>();
        } else {
            cp_wait<0>();
        }
        __syncthreads();

        const uint32_t bK_hi = su + 16384 + s * AT_STAGE;
        const uint32_t bK_lo = bK_hi + 8192;
        const uint32_t bV_hi = bK_hi + 16384;
        const uint32_t bV_lo = bK_hi + 24576;

        float sc[8][4];
#pragma unroll
        for (int nb = 0; nb < 8; nb++)
#pragma unroll
            for (int q = 0; q < 4; q++) sc[nb][q] = 0.f;
#pragma unroll
        for (int ks = 0; ks < 4; ks++) {
            const int cc = ks * 2 + (lane >> 4);
            uint32_t kh[4][4], kl[4][4];
#pragma unroll
            for (int nbp = 0; nbp < 4; nbp++) {
                const uint32_t off = toff128(nbp * 16 + (lane & 15), cc);
                ldm_x4(kh[nbp], bK_hi + off);
                ldm_x4(kl[nbp], bK_lo + off);
            }
            // term-major: 8 independent accumulators per term pass
#pragma unroll
            for (int nbp = 0; nbp < 4; nbp++) {
                mma16816(sc[2 * nbp],     qh[ks], kh[nbp][0], kh[nbp][2]);
                mma16816(sc[2 * nbp + 1], qh[ks], kh[nbp][1], kh[nbp][3]);
            }
#pragma unroll
            for (int nbp = 0; nbp < 4; nbp++) {
                mma16816(sc[2 * nbp],     qh[ks], kl[nbp][0], kl[nbp][2]);
                mma16816(sc[2 * nbp + 1], qh[ks], kl[nbp][1], kl[nbp][3]);
            }
#pragma unroll
            for (int nbp = 0; nbp < 4; nbp++) {
                mma16816(sc[2 * nbp],     ql[ks], kh[nbp][0], kh[nbp][2]);
                mma16816(sc[2 * nbp + 1], ql[ks], kh[nbp][1], kh[nbp][3]);
            }
        }

        if (jt == qt) {
            const int r0 = 16 * w + (lane >> 2);
#pragma unroll
            for (int nb = 0; nb < 8; nb++) {
                const int c0 = 8 * nb + 2 * (lane & 3);
                if (c0 > r0)     sc[nb][0] = -CUDART_INF_F;
                if (c0 + 1 > r0) sc[nb][1] = -CUDART_INF_F;
                if (c0 > r0 + 8)     sc[nb][2] = -CUDART_INF_F;
                if (c0 + 1 > r0 + 8) sc[nb][3] = -CUDART_INF_F;
            }
        }

        float tm0 = -CUDART_INF_F, tm1 = -CUDART_INF_F;
#pragma unroll
        for (int nb = 0; nb < 8; nb++) {
            tm0 = fmaxf(tm0, fmaxf(sc[nb][0], sc[nb][1]));
            tm1 = fmaxf(tm1, fmaxf(sc[nb][2], sc[nb][3]));
        }
        tm0 = fmaxf(tm0, __shfl_xor_sync(0xffffffffu, tm0, 1));
        tm0 = fmaxf(tm0, __shfl_xor_sync(0xffffffffu, tm0, 2));
        tm1 = fmaxf(tm1, __shfl_xor_sync(0xffffffffu, tm1, 1));
        tm1 = fmaxf(tm1, __shfl_xor_sync(0xffffffffu, tm1, 2));
        const float mn0 = fmaxf(mrow0, tm0), mn1 = fmaxf(mrow1, tm1);
        const float scl0 = __expf(mrow0 - mn0), scl1 = __expf(mrow1 - mn1);
        float ls0 = 0.f, ls1 = 0.f;
#pragma unroll
        for (int nb = 0; nb < 8; nb++) {
            sc[nb][0] = __expf(sc[nb][0] - mn0);
            sc[nb][1] = __expf(sc[nb][1] - mn0);
            sc[nb][2] = __expf(sc[nb][2] - mn1);
            sc[nb][3] = __expf(sc[nb][3] - mn1);
            ls0 += sc[nb][0] + sc[nb][1];
            ls1 += sc[nb][2] + sc[nb][3];
        }
        ls0 += __shfl_xor_sync(0xffffffffu, ls0, 1);
        ls0 += __shfl_xor_sync(0xffffffffu, ls0, 2);
        ls1 += __shfl_xor_sync(0xffffffffu, ls1, 1);
        ls1 += __shfl_xor_sync(0xffffffffu, ls1, 2);
        lrow0 = lrow0 * scl0 + ls0;
        lrow1 = lrow1 * scl1 + ls1;
        mrow0 = mn0; mrow1 = mn1;
#pragma unroll
        for (int nb = 0; nb < 8; nb++) {
            oc[nb][0] *= scl0; oc[nb][1] *= scl0;
            oc[nb][2] *= scl1; oc[nb][3] *= scl1;
        }

        uint32_t aph[4][4], apl[4][4];
#pragma unroll
        for (int ks = 0; ks < 4; ks++) {
            split2(sc[2 * ks][0],     sc[2 * ks][1],     aph[ks][0], apl[ks][0]);
            split2(sc[2 * ks][2],     sc[2 * ks][3],     aph[ks][1], apl[ks][1]);
            split2(sc[2 * ks + 1][0], sc[2 * ks + 1][1], aph[ks][2], apl[ks][2]);
            split2(sc[2 * ks + 1][2], sc[2 * ks + 1][3], aph[ks][3], apl[ks][3]);
        }

#pragma unroll
        for (int ks = 0; ks < 4; ks++) {
            uint32_t vh[4][4], vl[4][4];
#pragma unroll
            for (int dbp = 0; dbp < 4; dbp++) {
                const uint32_t off = toff128(16 * ks + (lane & 15), dbp * 2 + (lane >> 4));
                ldm_x4_t(vh[dbp], bV_hi + off);
                ldm_x4_t(vl[dbp], bV_lo + off);
            }
            // term-major PV
#pragma unroll
            for (int dbp = 0; dbp < 4; dbp++) {
                mma16816(oc[2 * dbp],     aph[ks], vh[dbp][0], vh[dbp][1]);
                mma16816(oc[2 * dbp + 1], aph[ks], vh[dbp][2], vh[dbp][3]);
            }
#pragma unroll
            for (int dbp = 0; dbp < 4; dbp++) {
                mma16816(oc[2 * dbp],     aph[ks], vl[dbp][0], vl[dbp][1]);
                mma16816(oc[2 * dbp + 1], aph[ks], vl[dbp][2], vl[dbp][3]);
            }
#pragma unroll
            for (int dbp = 0; dbp < 4; dbp++) {
                mma16816(oc[2 * dbp],     apl[ks], vh[dbp][0], vh[dbp][1]);
                mma16816(oc[2 * dbp + 1], apl[ks], vh[dbp][2], vh[dbp][3]);
            }
        }
        __syncthreads();
    }

    const float inv0 = 1.f / lrow0, inv1 = 1.f / lrow1;
    const size_t r0 = rowQ0 + 16 * w + (lane >> 2);
#pragma unroll
    for (int nb = 0; nb < 8; nb++) {
        const int col = hoff + 8 * nb + 2 * (lane & 3);
        uint32_t hw, lw;
        split2(oc[nb][0] * inv0, oc[nb][1] * inv0, hw, lw);
        *(uint32_t*)&Chi[r0 * E_ + col] = hw;
        *(uint32_t*)&Clo[r0 * E_ + col] = lw;
        split2(oc[nb][2] * inv1, oc[nb][3] * inv1, hw, lw);
        *(uint32_t*)&Chi[(r0 + 8) * E_ + col] = hw;
        *(uint32_t*)&Clo[(r0 + 8) * E_ + col] = lw;
    }
}

// ---------------------------------------------------------------------------
extern "C" void kernel_launch(void* const* d_in, const int* in_sizes, int n_in,
                              void* d_out, int out_size)
{
    const float* X  = (const float*)d_in[0];
    const float* Wq = (const float*)d_in[1];
    const float* bq = (const float*)d_in[2];
    const float* Wk = (const float*)d_in[3];
    const float* bk = (const float*)d_in[4];
    const float* Wv = (const float*)d_in[5];
    const float* bv = (const float*)d_in[6];
    const float* Wo = (const float*)d_in[7];
    const float* bo = (const float*)d_in[8];
    float* out = (float*)d_out;

    __nv_bfloat16 *Ahi, *Alo, *Qhi, *Qlo, *Khi, *Klo, *Vhi, *Vlo;
    __nv_bfloat16 *WhiB, *WloB;
    cudaGetSymbolAddress((void**)&Ahi, g_Ahi);
    cudaGetSymbolAddress((void**)&Alo, g_Alo);
    cudaGetSymbolAddress((void**)&WhiB, g_Whi);
    cudaGetSymbolAddress((void**)&WloB, g_Wlo);
    cudaGetSymbolAddress((void**)&Qhi, g_Qhi);
    cudaGetSymbolAddress((void**)&Qlo, g_Qlo);
    cudaGetSymbolAddress((void**)&Khi, g_Khi);
    cudaGetSymbolAddress((void**)&Klo, g_Klo);
    cudaGetSymbolAddress((void**)&Vhi, g_Vhi);
    cudaGetSymbolAddress((void**)&Vlo, g_Vlo);
    const size_t WSZ = (size_t)E_ * E_;

    cudaFuncSetAttribute(gemm_tc, cudaFuncAttributeMaxDynamicSharedMemorySize, SMEM_GEMM);
    cudaFuncSetAttribute(attn_tc, cudaFuncAttributeMaxDynamicSharedMemorySize, SMEM_ATTN);

    const int nX4 = (M_ * E_) / 4;
    const int nW4 = (E_ * E_) / 4;

    SplitJobs sj;
    sj.src[0] = Wq; sj.src[1] = Wk; sj.src[2] = Wv; sj.src[3] = Wo;
    for (int i = 0; i < 4; i++) { sj.hi[i] = WhiB + i * WSZ; sj.lo[i] = WloB + i * WSZ; }
    split_weights<<<dim3((nW4 + 255) / 256, 4), 256>>>(sj, nW4);
    split_fp32<<<(nX4 + 255) / 256, 256>>>(X, Ahi, Alo, nX4);

    // batched Q,K,V projections
    GemmJobs qkv;
    qkv.Whi[0] = WhiB;           qkv.Wlo[0] = WloB;
    qkv.Whi[1] = WhiB + WSZ;     qkv.Wlo[1] = WloB + WSZ;
    qkv.Whi[2] = WhiB + 2 * WSZ; qkv.Wlo[2] = WloB + 2 * WSZ;
    qkv.bias[0] = bq; qkv.bias[1] = bk; qkv.bias[2] = bv;
    qkv.Ohi[0] = Qhi; qkv.Olo[0] = Qlo;
    qkv.Ohi[1] = Khi; qkv.Olo[1] = Klo;
    qkv.Ohi[2] = Vhi; qkv.Olo[2] = Vlo;
    qkv.C[0] = qkv.C[1] = qkv.C[2] = nullptr;
    qkv.alpha[0] = SCALING; qkv.alpha[1] = 1.f; qkv.alpha[2] = 1.f;
    gemm_tc<<<dim3(E_ / 128, M_ / 128, 3), 256, SMEM_GEMM>>>(Ahi, Alo, qkv);

    dim3 ag(T_ / 64, B_ * H_);
    attn_tc<<<ag, 128, SMEM_ATTN>>>(Qhi, Qlo, Khi, Klo, Vhi, Vlo, Ahi, Alo);

    // output projection (fp32 out)
    GemmJobs oj;
    oj.Whi[0] = WhiB + 3 * WSZ; oj.Wlo[0] = WloB + 3 * WSZ;
    oj.bias[0] = bo;
    oj.Ohi[0] = nullptr; oj.Olo[0] = nullptr;
    oj.C[0] = out;
    oj.alpha[0] = 1.f;
    oj.Whi[1] = oj.Whi[2] = nullptr; oj.Wlo[1] = oj.Wlo[2] = nullptr;
    oj.bias[1] = oj.bias[2] = nullptr;
    oj.Ohi[1] = oj.Ohi[2] = nullptr; oj.Olo[1] = oj.Olo[2] = nullptr;
    oj.C[1] = oj.C[2] = nullptr;
    oj.alpha[1] = oj.alpha[2] = 0.f;
    gemm_tc<<<dim3(E_ / 128, M_ / 128, 1), 256, SMEM_GEMM>>>(Ahi, Alo, oj);
}

// round 13
// speedup vs baseline: 1.1105x; 1.1105x over previous
#include <cuda_runtime.h>
#include <cuda_bf16.h>
#include <cuda_fp16.h>
#include <math_constants.h>
#include <cstdint>

#define B_ 2
#define T_ 2048
#define E_ 2048
#define H_ 32
#define D_ 64
#define M_ (B_ * T_)
#define SCALING 0.125f

// ---------------- scratch (__device__ globals; allocation-free rule) --------
__device__ __half g_Ahi[M_ * E_];          // fp16 split of X; later ctx
__device__ __half g_Alo[M_ * E_];
__device__ __half g_Whi[4][E_ * E_];       // q,k,v,o weight fp16 splits
__device__ __half g_Wlo[4][E_ * E_];
__device__ __nv_bfloat16 g_Qhi[M_ * E_];   // attention operands stay bf16
__device__ __nv_bfloat16 g_Qlo[M_ * E_];
__device__ __nv_bfloat16 g_Khi[M_ * E_];
__device__ __nv_bfloat16 g_Klo[M_ * E_];
__device__ __nv_bfloat16 g_Vhi[M_ * E_];
__device__ __nv_bfloat16 g_Vlo[M_ * E_];

// ---------------- helpers ---------------------------------------------------
__device__ __forceinline__ uint32_t smem_u32(const void* p) {
    uint32_t a;
    asm("{ .reg .u64 t; cvta.to.shared.u64 t, %1; cvt.u32.u64 %0, t; }" : "=r"(a) : "l"(p));
    return a;
}
__device__ __forceinline__ void cp16(uint32_t dst, const void* src) {
    asm volatile("cp.async.cg.shared.global [%0], [%1], 16;" :: "r"(dst), "l"(src));
}
__device__ __forceinline__ void cp_commit() {
    asm volatile("cp.async.commit_group;" ::: "memory");
}
template <int N>
__device__ __forceinline__ void cp_wait() {
    asm volatile("cp.async.wait_group %0;" :: "n"(N) : "memory");
}
__device__ __forceinline__ void ldm_x4(uint32_t* d, uint32_t addr) {
    asm volatile("ldmatrix.sync.aligned.m8n8.x4.shared.b16 {%0,%1,%2,%3}, [%4];"
                 : "=r"(d[0]), "=r"(d[1]), "=r"(d[2]), "=r"(d[3]) : "r"(addr));
}
__device__ __forceinline__ void ldm_x4_t(uint32_t* d, uint32_t addr) {
    asm volatile("ldmatrix.sync.aligned.m8n8.x4.trans.shared.b16 {%0,%1,%2,%3}, [%4];"
                 : "=r"(d[0]), "=r"(d[1]), "=r"(d[2]), "=r"(d[3]) : "r"(addr));
}
// bf16 mma (attention)
__device__ __forceinline__ void mma16816(float* c, const uint32_t* a, uint32_t b0, uint32_t b1) {
    asm volatile("mma.sync.aligned.m16n8k16.row.col.f32.bf16.bf16.f32 "
                 "{%0,%1,%2,%3}, {%4,%5,%6,%7}, {%8,%9}, {%0,%1,%2,%3};"
                 : "+f"(c[0]), "+f"(c[1]), "+f"(c[2]), "+f"(c[3])
                 : "r"(a[0]), "r"(a[1]), "r"(a[2]), "r"(a[3]), "r"(b0), "r"(b1));
}
// fp16 mma (GEMMs)
__device__ __forceinline__ void mma16816h(float* c, const uint32_t* a, uint32_t b0, uint32_t b1) {
    asm volatile("mma.sync.aligned.m16n8k16.row.col.f32.f16.f16.f32 "
                 "{%0,%1,%2,%3}, {%4,%5,%6,%7}, {%8,%9}, {%0,%1,%2,%3};"
                 : "+f"(c[0]), "+f"(c[1]), "+f"(c[2]), "+f"(c[3])
                 : "r"(a[0]), "r"(a[1]), "r"(a[2]), "r"(a[3]), "r"(b0), "r"(b1));
}
__device__ __forceinline__ uint32_t pack_bf16(float lo, float hi) {
    uint32_t r;
    asm("cvt.rn.bf16x2.f32 %0, %1, %2;" : "=r"(r) : "f"(hi), "f"(lo));
    return r;
}
// bf16 hi/lo split of a pair
__device__ __forceinline__ void split2(float a, float b, uint32_t& hw, uint32_t& lw) {
    hw = pack_bf16(a, b);
    float ha = __uint_as_float(hw << 16);
    float hb = __uint_as_float(hw & 0xffff0000u);
    lw = pack_bf16(a - ha, b - hb);
}
// fp16 hi/lo split of a pair
__device__ __forceinline__ void split2h(float a, float b, uint32_t& hw, uint32_t& lw) {
    __half2 h = __floats2half2_rn(a, b);
    hw = *reinterpret_cast<uint32_t*>(&h);
    float ha = __half2float(__low2half(h));
    float hb = __half2float(__high2half(h));
    __half2 l = __floats2half2_rn(a - ha, b - hb);
    lw = *reinterpret_cast<uint32_t*>(&l);
}
// swizzle for 32-col (64B-row) 16-bit tiles
__device__ __forceinline__ uint32_t tile_off(int r, int c) {
    return (uint32_t)(r * 64 + ((c ^ ((r >> 1) & 3)) << 4));
}
// swizzle for 64-col (128B-row) 16-bit tiles
__device__ __forceinline__ uint32_t toff128(int r, int c) {
    return (uint32_t)(r * 128 + ((c ^ (r & 7)) << 4));
}

// ---------------------------------------------------------------------------
// splits (fp16 outputs)
// ---------------------------------------------------------------------------
__global__ __launch_bounds__(256) void split_fp32(
    const float* __restrict__ x, __half* __restrict__ hi,
    __half* __restrict__ lo, int n4)
{
    int i = blockIdx.x * 256 + threadIdx.x;
    if (i >= n4) return;
    float4 v = ((const float4*)x)[i];
    uint32_t h0, l0, h1, l1;
    split2h(v.x, v.y, h0, l0);
    split2h(v.z, v.w, h1, l1);
    ((uint2*)hi)[i] = make_uint2(h0, h1);
    ((uint2*)lo)[i] = make_uint2(l0, l1);
}

struct SplitJobs {
    const float* src[4];
    __half* hi[4];
    __half* lo[4];
};
__global__ __launch_bounds__(256) void split_weights(SplitJobs jobs, int n4)
{
    int i = blockIdx.x * 256 + threadIdx.x;
    if (i >= n4) return;
    const int w = blockIdx.y;
    float4 v = ((const float4*)jobs.src[w])[i];
    uint32_t h0, l0, h1, l1;
    split2h(v.x, v.y, h0, l0);
    split2h(v.z, v.w, h1, l1);
    ((uint2*)jobs.hi[w])[i] = make_uint2(h0, h1);
    ((uint2*)jobs.lo[w])[i] = make_uint2(l0, l1);
}

// ---------------------------------------------------------------------------
// fp16 split GEMM: CTA 128x128, warp 32x64, BK=32, 3 stages, 2 CTAs/SM.
// Per-job nt: 3-pass (Ahi*Whi + Alo*Whi + Ahi*Wlo, err~2^-22) for Q,K;
//             2-pass (Ahi*Whi + Alo*Whi = A*W_f16, err~2^-12)  for V,O.
// Stage 32KB: Ahi 8K | Alo 8K | Whi 8K | Wlo 8K (Wlo unused when nt=2)
// ---------------------------------------------------------------------------
#define GSTAGE 32768
#define SMEM_GEMM (3 * GSTAGE)
#define NCH32 (E_ / 32)

struct GemmJobs {
    const __half* Whi[3];
    const __half* Wlo[3];
    const float* bias[3];
    __nv_bfloat16* Ohi[3];
    __nv_bfloat16* Olo[3];
    float* C[3];
    float alpha[3];
    int nt[3];
};

__global__ __launch_bounds__(256, 2) void gemm_tc(
    const __half* __restrict__ Ahi, const __half* __restrict__ Alo,
    GemmJobs jobs)
{
    extern __shared__ __align__(1024) char smem[];
    const uint32_t su = smem_u32(smem);
    const int tid = threadIdx.x, wid = tid >> 5, lane = tid & 31;
    const int brow = blockIdx.y * 128, bcol = blockIdx.x * 128;
    const int jz = blockIdx.z;
    const __half* Whi = jobs.Whi[jz];
    const __half* Wlo = jobs.Wlo[jz];
    const bool nt3 = (jobs.nt[jz] == 3);
    const int wm = wid & 3;        // warp row block (32 rows)
    const int wn = wid >> 2;       // warp col block (64 cols)

    float acc[2][8][4];
#pragma unroll
    for (int mt = 0; mt < 2; mt++)
#pragma unroll
        for (int j = 0; j < 8; j++)
#pragma unroll
            for (int q = 0; q < 4; q++) acc[mt][j][q] = 0.f;

    auto load_part = [&](int k0, int s, int p) {
        const uint32_t base = su + s * GSTAGE;
        int idx = tid + p * 256;           // 0..511: 128 rows x 4 chunks
        int r = idx >> 2, c = idx & 3;
        uint32_t off = tile_off(r, c);
        size_t ga = (size_t)(brow + r) * E_ + k0 + c * 8;
        size_t gw = (size_t)(bcol + r) * E_ + k0 + c * 8;
        cp16(base +         off, Ahi + ga);
        cp16(base +  8192 + off, Alo + ga);
        cp16(base + 16384 + off, Whi + gw);
        if (nt3) cp16(base + 24576 + off, Wlo + gw);
    };
    auto load_chunk = [&](int k0, int s) {
#pragma unroll
        for (int p = 0; p < 2; p++) load_part(k0, s, p);
        cp_commit();
    };

    load_chunk(0, 0);
    load_chunk(32, 1);

    for (int k = 0; k < NCH32; k++) {
        if (k + 1 < NCH32) { cp_wait<1>(); } else { cp_wait<0>(); }
        __syncthreads();
        const bool pre = (k + 2 < NCH32);
        const int ps = (k + 2) % 3;
        const int pk = (k + 2) * 32;

        const uint32_t bA_hi = su + (k % 3) * GSTAGE;
        const uint32_t bA_lo = bA_hi + 8192;
        const uint32_t bW_hi = bA_hi + 16384;
        const uint32_t bW_lo = bA_hi + 24576;

#pragma unroll
        for (int ks = 0; ks < 2; ks++) {
            if (pre) load_part(pk, ps, ks);
            const int cc = ks * 2 + (lane >> 4);
            uint32_t ah[2][4], al[2][4];
#pragma unroll
            for (int mt = 0; mt < 2; mt++) {
                const uint32_t off = tile_off(wm * 32 + mt * 16 + (lane & 15), cc);
                ldm_x4(ah[mt], bA_hi + off);
                ldm_x4(al[mt], bA_lo + off);
            }
            uint32_t bh[4][4];
#pragma unroll
            for (int nb = 0; nb < 4; nb++) {
                const uint32_t off = tile_off(wn * 64 + nb * 16 + (lane & 15), cc);
                ldm_x4(bh[nb], bW_hi + off);
            }
            // pass 1: Ahi * Whi
#pragma unroll
            for (int mt = 0; mt < 2; mt++)
#pragma unroll
                for (int j = 0; j < 8; j++) {
                    const int nb = j >> 1, sel = j & 1;
                    mma16816h(acc[mt][j], ah[mt], bh[nb][sel], bh[nb][sel + 2]);
                }
            // pass 2: Alo * Whi
#pragma unroll
            for (int mt = 0; mt < 2; mt++)
#pragma unroll
                for (int j = 0; j < 8; j++) {
                    const int nb = j >> 1, sel = j & 1;
                    mma16816h(acc[mt][j], al[mt], bh[nb][sel], bh[nb][sel + 2]);
                }
            // pass 3 (Q,K only): Ahi * Wlo
            if (nt3) {
                uint32_t bl[4][4];
#pragma unroll
                for (int nb = 0; nb < 4; nb++) {
                    const uint32_t off = tile_off(wn * 64 + nb * 16 + (lane & 15), cc);
                    ldm_x4(bl[nb], bW_lo + off);
                }
#pragma unroll
                for (int mt = 0; mt < 2; mt++)
#pragma unroll
                    for (int j = 0; j < 8; j++) {
                        const int nb = j >> 1, sel = j & 1;
                        mma16816h(acc[mt][j], ah[mt], bl[nb][sel], bl[nb][sel + 2]);
                    }
            }
        }
        if (pre) cp_commit();
    }

    const float alpha = jobs.alpha[jz];
    const float* bias = jobs.bias[jz];
    __nv_bfloat16* Ohi = jobs.Ohi[jz];
    __nv_bfloat16* Olo = jobs.Olo[jz];
    float* C = jobs.C[jz];
#pragma unroll
    for (int mt = 0; mt < 2; mt++) {
        const int r0 = brow + wm * 32 + mt * 16 + (lane >> 2);
#pragma unroll
        for (int j = 0; j < 8; j++) {
            const int col = bcol + wn * 64 + j * 8 + (lane & 3) * 2;
            const float bx = bias[col], by = bias[col + 1];
            float v00 = alpha * (acc[mt][j][0] + bx);
            float v01 = alpha * (acc[mt][j][1] + by);
            float v10 = alpha * (acc[mt][j][2] + bx);
            float v11 = alpha * (acc[mt][j][3] + by);
            if (Ohi) {   // QKV: bf16 split output for attention
                uint32_t hw, lw;
                split2(v00, v01, hw, lw);
                *(uint32_t*)&Ohi[(size_t)r0 * E_ + col] = hw;
                *(uint32_t*)&Olo[(size_t)r0 * E_ + col] = lw;
                split2(v10, v11, hw, lw);
                *(uint32_t*)&Ohi[(size_t)(r0 + 8) * E_ + col] = hw;
                *(uint32_t*)&Olo[(size_t)(r0 + 8) * E_ + col] = lw;
            } else {     // O-proj: fp32 final output
                *(float2*)&C[(size_t)r0 * E_ + col]       = make_float2(v00, v01);
                *(float2*)&C[(size_t)(r0 + 8) * E_ + col] = make_float2(v10, v11);
            }
        }
    }
}

// ---------------------------------------------------------------------------
// Tensor-core flash attention (bf16 3-pass, unchanged mainloop; epilogue now
// writes fp16-split ctx for the O projection).
// ---------------------------------------------------------------------------
#define AT_STAGE 32768
#define SMEM_ATTN (16384 + 2 * AT_STAGE)

__global__ __launch_bounds__(128, 1) void attn_tc(
    const __nv_bfloat16* __restrict__ Qhi, const __nv_bfloat16* __restrict__ Qlo,
    const __nv_bfloat16* __restrict__ Khi, const __nv_bfloat16* __restrict__ Klo,
    const __nv_bfloat16* __restrict__ Vhi, const __nv_bfloat16* __restrict__ Vlo,
    __half* __restrict__ Chi, __half* __restrict__ Clo)
{
    extern __shared__ __align__(1024) char smem[];
    const uint32_t su = smem_u32(smem);
    const int tid = threadIdx.x, w = tid >> 5, lane = tid & 31;
    const int qt = gridDim.x - 1 - blockIdx.x;
    const int bh = blockIdx.y;
    const int b = bh >> 5, h = bh & 31;

    const size_t rowQ0 = (size_t)(b * T_ + qt * 64);
    const size_t rowK0 = (size_t)(b * T_);
    const int hoff = h * 64;

    auto load_q = [&]() {
#pragma unroll
        for (int it = 0; it < 4; it++) {
            int idx = tid + it * 128;
            int r = idx >> 3, c = idx & 7;
            uint32_t off = toff128(r, c);
            size_t g = (rowQ0 + r) * E_ + hoff + c * 8;
            cp16(su +        off, Qhi + g);
            cp16(su + 8192 + off, Qlo + g);
        }
    };
    auto load_kv = [&](int jt, int s) {
        const uint32_t base = su + 16384 + s * AT_STAGE;
#pragma unroll
        for (int it = 0; it < 4; it++) {
            int idx = tid + it * 128;
            int r = idx >> 3, c = idx & 7;
            uint32_t off = toff128(r, c);
            size_t g = (rowK0 + jt * 64 + r) * E_ + hoff + c * 8;
            cp16(base +         off, Khi + g);
            cp16(base +  8192 + off, Klo + g);
            cp16(base + 16384 + off, Vhi + g);
            cp16(base + 24576 + off, Vlo + g);
        }
    };

    load_q();
    load_kv(0, 0);
    cp_commit();
    cp_wait<0>();
    __syncthreads();

    uint32_t qh[4][4], ql[4][4];
#pragma unroll
    for (int ks = 0; ks < 4; ks++) {
        const uint32_t off = toff128(16 * w + (lane & 15), ks * 2 + (lane >> 4));
        ldm_x4(qh[ks], su + off);
        ldm_x4(ql[ks], su + 8192 + off);
    }

    float oc[8][4];
#pragma unroll
    for (int nb = 0; nb < 8; nb++)
#pragma unroll
        for (int q = 0; q < 4; q++) oc[nb][q] = 0.f;
    float mrow0 = -CUDART_INF_F, mrow1 = -CUDART_INF_F;
    float lrow0 = 0.f, lrow1 = 0.f;

    for (int jt = 0; jt <= qt; jt++) {
        const int s = jt & 1;
        if (jt + 1 <= qt) {
            load_kv(jt + 1, s ^ 1);
            cp_commit();
            cp_wait<1>();
        } else {
            cp_wait<0>();
        }
        __syncthreads();

        const uint32_t bK_hi = su + 16384 + s * AT_STAGE;
        const uint32_t bK_lo = bK_hi + 8192;
        const uint32_t bV_hi = bK_hi + 16384;
        const uint32_t bV_lo = bK_hi + 24576;

        float sc[8][4];
#pragma unroll
        for (int nb = 0; nb < 8; nb++)
#pragma unroll
            for (int q = 0; q < 4; q++) sc[nb][q] = 0.f;
#pragma unroll
        for (int ks = 0; ks < 4; ks++) {
            const int cc = ks * 2 + (lane >> 4);
            uint32_t kh[4][4], kl[4][4];
#pragma unroll
            for (int nbp = 0; nbp < 4; nbp++) {
                const uint32_t off = toff128(nbp * 16 + (lane & 15), cc);
                ldm_x4(kh[nbp], bK_hi + off);
                ldm_x4(kl[nbp], bK_lo + off);
            }
#pragma unroll
            for (int nbp = 0; nbp < 4; nbp++) {
                mma16816(sc[2 * nbp],     qh[ks], kh[nbp][0], kh[nbp][2]);
                mma16816(sc[2 * nbp + 1], qh[ks], kh[nbp][1], kh[nbp][3]);
            }
#pragma unroll
            for (int nbp = 0; nbp < 4; nbp++) {
                mma16816(sc[2 * nbp],     qh[ks], kl[nbp][0], kl[nbp][2]);
                mma16816(sc[2 * nbp + 1], qh[ks], kl[nbp][1], kl[nbp][3]);
            }
#pragma unroll
            for (int nbp = 0; nbp < 4; nbp++) {
                mma16816(sc[2 * nbp],     ql[ks], kh[nbp][0], kh[nbp][2]);
                mma16816(sc[2 * nbp + 1], ql[ks], kh[nbp][1], kh[nbp][3]);
            }
        }

        if (jt == qt) {
            const int r0 = 16 * w + (lane >> 2);
#pragma unroll
            for (int nb = 0; nb < 8; nb++) {
                const int c0 = 8 * nb + 2 * (lane & 3);
                if (c0 > r0)     sc[nb][0] = -CUDART_INF_F;
                if (c0 + 1 > r0) sc[nb][1] = -CUDART_INF_F;
                if (c0 > r0 + 8)     sc[nb][2] = -CUDART_INF_F;
                if (c0 + 1 > r0 + 8) sc[nb][3] = -CUDART_INF_F;
            }
        }

        float tm0 = -CUDART_INF_F, tm1 = -CUDART_INF_F;
#pragma unroll
        for (int nb = 0; nb < 8; nb++) {
            tm0 = fmaxf(tm0, fmaxf(sc[nb][0], sc[nb][1]));
            tm1 = fmaxf(tm1, fmaxf(sc[nb][2], sc[nb][3]));
        }
        tm0 = fmaxf(tm0, __shfl_xor_sync(0xffffffffu, tm0, 1));
        tm0 = fmaxf(tm0, __shfl_xor_sync(0xffffffffu, tm0, 2));
        tm1 = fmaxf(tm1, __shfl_xor_sync(0xffffffffu, tm1, 1));
        tm1 = fmaxf(tm1, __shfl_xor_sync(0xffffffffu, tm1, 2));
        const float mn0 = fmaxf(mrow0, tm0), mn1 = fmaxf(mrow1, tm1);
        const float scl0 = __expf(mrow0 - mn0), scl1 = __expf(mrow1 - mn1);
        float ls0 = 0.f, ls1 = 0.f;
#pragma unroll
        for (int nb = 0; nb < 8; nb++) {
            sc[nb][0] = __expf(sc[nb][0] - mn0);
            sc[nb][1] = __expf(sc[nb][1] - mn0);
            sc[nb][2] = __expf(sc[nb][2] - mn1);
            sc[nb][3] = __expf(sc[nb][3] - mn1);
            ls0 += sc[nb][0] + sc[nb][1];
            ls1 += sc[nb][2] + sc[nb][3];
        }
        ls0 += __shfl_xor_sync(0xffffffffu, ls0, 1);
        ls0 += __shfl_xor_sync(0xffffffffu, ls0, 2);
        ls1 += __shfl_xor_sync(0xffffffffu, ls1, 1);
        ls1 += __shfl_xor_sync(0xffffffffu, ls1, 2);
        lrow0 = lrow0 * scl0 + ls0;
        lrow1 = lrow1 * scl1 + ls1;
        mrow0 = mn0; mrow1 = mn1;
#pragma unroll
        for (int nb = 0; nb < 8; nb++) {
            oc[nb][0] *= scl0; oc[nb][1] *= scl0;
            oc[nb][2] *= scl1; oc[nb][3] *= scl1;
        }

        uint32_t aph[4][4], apl[4][4];
#pragma unroll
        for (int ks = 0; ks < 4; ks++) {
            split2(sc[2 * ks][0],     sc[2 * ks][1],     aph[ks][0], apl[ks][0]);
            split2(sc[2 * ks][2],     sc[2 * ks][3],     aph[ks][1], apl[ks][1]);
            split2(sc[2 * ks + 1][0], sc[2 * ks + 1][1], aph[ks][2], apl[ks][2]);
            split2(sc[2 * ks + 1][2], sc[2 * ks + 1][3], aph[ks][3], apl[ks][3]);
        }

#pragma unroll
        for (int ks = 0; ks < 4; ks++) {
            uint32_t vh[4][4], vl[4][4];
#pragma unroll
            for (int dbp = 0; dbp < 4; dbp++) {
                const uint32_t off = toff128(16 * ks + (lane & 15), dbp * 2 + (lane >> 4));
                ldm_x4_t(vh[dbp], bV_hi + off);
                ldm_x4_t(vl[dbp], bV_lo + off);
            }
#pragma unroll
            for (int dbp = 0; dbp < 4; dbp++) {
                mma16816(oc[2 * dbp],     aph[ks], vh[dbp][0], vh[dbp][1]);
                mma16816(oc[2 * dbp + 1], aph[ks], vh[dbp][2], vh[dbp][3]);
            }
#pragma unroll
            for (int dbp = 0; dbp < 4; dbp++) {
                mma16816(oc[2 * dbp],     aph[ks], vl[dbp][0], vl[dbp][1]);
                mma16816(oc[2 * dbp + 1], aph[ks], vl[dbp][2], vl[dbp][3]);
            }
#pragma unroll
            for (int dbp = 0; dbp < 4; dbp++) {
                mma16816(oc[2 * dbp],     apl[ks], vh[dbp][0], vh[dbp][1]);
                mma16816(oc[2 * dbp + 1], apl[ks], vh[dbp][2], vh[dbp][3]);
            }
        }
        __syncthreads();
    }

    // epilogue: ctx = O / l -> fp16 split (O-projection input format)
    const float inv0 = 1.f / lrow0, inv1 = 1.f / lrow1;
    const size_t r0 = rowQ0 + 16 * w + (lane >> 2);
#pragma unroll
    for (int nb = 0; nb < 8; nb++) {
        const int col = hoff + 8 * nb + 2 * (lane & 3);
        uint32_t hw, lw;
        split2h(oc[nb][0] * inv0, oc[nb][1] * inv0, hw, lw);
        *(uint32_t*)&Chi[r0 * E_ + col] = hw;
        *(uint32_t*)&Clo[r0 * E_ + col] = lw;
        split2h(oc[nb][2] * inv1, oc[nb][3] * inv1, hw, lw);
        *(uint32_t*)&Chi[(r0 + 8) * E_ + col] = hw;
        *(uint32_t*)&Clo[(r0 + 8) * E_ + col] = lw;
    }
}

// ---------------------------------------------------------------------------
extern "C" void kernel_launch(void* const* d_in, const int* in_sizes, int n_in,
                              void* d_out, int out_size)
{
    const float* X  = (const float*)d_in[0];
    const float* Wq = (const float*)d_in[1];
    const float* bq = (const float*)d_in[2];
    const float* Wk = (const float*)d_in[3];
    const float* bk = (const float*)d_in[4];
    const float* Wv = (const float*)d_in[5];
    const float* bv = (const float*)d_in[6];
    const float* Wo = (const float*)d_in[7];
    const float* bo = (const float*)d_in[8];
    float* out = (float*)d_out;

    __half *Ahi, *Alo, *WhiB, *WloB;
    __nv_bfloat16 *Qhi, *Qlo, *Khi, *Klo, *Vhi, *Vlo;
    cudaGetSymbolAddress((void**)&Ahi, g_Ahi);
    cudaGetSymbolAddress((void**)&Alo, g_Alo);
    cudaGetSymbolAddress((void**)&WhiB, g_Whi);
    cudaGetSymbolAddress((void**)&WloB, g_Wlo);
    cudaGetSymbolAddress((void**)&Qhi, g_Qhi);
    cudaGetSymbolAddress((void**)&Qlo, g_Qlo);
    cudaGetSymbolAddress((void**)&Khi, g_Khi);
    cudaGetSymbolAddress((void**)&Klo, g_Klo);
    cudaGetSymbolAddress((void**)&Vhi, g_Vhi);
    cudaGetSymbolAddress((void**)&Vlo, g_Vlo);
    const size_t WSZ = (size_t)E_ * E_;

    cudaFuncSetAttribute(gemm_tc, cudaFuncAttributeMaxDynamicSharedMemorySize, SMEM_GEMM);
    cudaFuncSetAttribute(attn_tc, cudaFuncAttributeMaxDynamicSharedMemorySize, SMEM_ATTN);

    const int nX4 = (M_ * E_) / 4;
    const int nW4 = (E_ * E_) / 4;

    SplitJobs sj;
    sj.src[0] = Wq; sj.src[1] = Wk; sj.src[2] = Wv; sj.src[3] = Wo;
    for (int i = 0; i < 4; i++) { sj.hi[i] = WhiB + i * WSZ; sj.lo[i] = WloB + i * WSZ; }
    split_weights<<<dim3((nW4 + 255) / 256, 4), 256>>>(sj, nW4);
    split_fp32<<<(nX4 + 255) / 256, 256>>>(X, Ahi, Alo, nX4);

    // batched Q,K,V projections (Q,K: 3-pass; V: 2-pass)
    GemmJobs qkv;
    qkv.Whi[0] = WhiB;           qkv.Wlo[0] = WloB;
    qkv.Whi[1] = WhiB + WSZ;     qkv.Wlo[1] = WloB + WSZ;
    qkv.Whi[2] = WhiB + 2 * WSZ; qkv.Wlo[2] = WloB + 2 * WSZ;
    qkv.bias[0] = bq; qkv.bias[1] = bk; qkv.bias[2] = bv;
    qkv.Ohi[0] = Qhi; qkv.Olo[0] = Qlo;
    qkv.Ohi[1] = Khi; qkv.Olo[1] = Klo;
    qkv.Ohi[2] = Vhi; qkv.Olo[2] = Vlo;
    qkv.C[0] = qkv.C[1] = qkv.C[2] = nullptr;
    qkv.alpha[0] = SCALING; qkv.alpha[1] = 1.f; qkv.alpha[2] = 1.f;
    qkv.nt[0] = 3; qkv.nt[1] = 3; qkv.nt[2] = 2;
    gemm_tc<<<dim3(E_ / 128, M_ / 128, 3), 256, SMEM_GEMM>>>(Ahi, Alo, qkv);

    dim3 ag(T_ / 64, B_ * H_);
    attn_tc<<<ag, 128, SMEM_ATTN>>>(Qhi, Qlo, Khi, Klo, Vhi, Vlo, Ahi, Alo);

    // output projection (2-pass, fp32 out)
    GemmJobs oj;
    oj.Whi[0] = WhiB + 3 * WSZ; oj.Wlo[0] = WloB + 3 * WSZ;
    oj.bias[0] = bo;
    oj.Ohi[0] = nullptr; oj.Olo[0] = nullptr;
    oj.C[0] = out;
    oj.alpha[0] = 1.f;
    oj.nt[0] = 2;
    oj.Whi[1] = oj.Whi[2] = nullptr; oj.Wlo[1] = oj.Wlo[2] = nullptr;
    oj.bias[1] = oj.bias[2] = nullptr;
    oj.Ohi[1] = oj.Ohi[2] = nullptr; oj.Olo[1] = oj.Olo[2] = nullptr;
    oj.C[1] = oj.C[2] = nullptr;
    oj.alpha[1] = oj.alpha[2] = 0.f;
    oj.nt[1] = oj.nt[2] = 2;
    gemm_tc<<<dim3(E_ / 128, M_ / 128, 1), 256, SMEM_GEMM>>>(Ahi, Alo, oj);
}

// round 16
// speedup vs baseline: 1.1424x; 1.0288x over previous
#include <cuda_runtime.h>
#include <cuda_fp16.h>
#include <math_constants.h>
#include <cstdint>

#define B_ 2
#define T_ 2048
#define E_ 2048
#define H_ 32
#define D_ 64
#define M_ (B_ * T_)
#define SCALING 0.125f

// ---------------- scratch (__device__ globals; allocation-free rule) --------
__device__ __half g_Ahi[M_ * E_];          // fp16 split of X; later ctx
__device__ __half g_Alo[M_ * E_];
__device__ __half g_Whi[4][E_ * E_];       // q,k,v,o weight fp16 splits
__device__ __half g_Wlo[4][E_ * E_];
__device__ __half g_Qhi[M_ * E_];          // fp16-split Q,K; plain fp16 V
__device__ __half g_Qlo[M_ * E_];
__device__ __half g_Khi[M_ * E_];
__device__ __half g_Klo[M_ * E_];
__device__ __half g_V[M_ * E_];

// ---------------- helpers ---------------------------------------------------
__device__ __forceinline__ uint32_t smem_u32(const void* p) {
    uint32_t a;
    asm("{ .reg .u64 t; cvta.to.shared.u64 t, %1; cvt.u32.u64 %0, t; }" : "=r"(a) : "l"(p));
    return a;
}
__device__ __forceinline__ void cp16(uint32_t dst, const void* src) {
    asm volatile("cp.async.cg.shared.global [%0], [%1], 16;" :: "r"(dst), "l"(src));
}
__device__ __forceinline__ void cp_commit() {
    asm volatile("cp.async.commit_group;" ::: "memory");
}
template <int N>
__device__ __forceinline__ void cp_wait() {
    asm volatile("cp.async.wait_group %0;" :: "n"(N) : "memory");
}
__device__ __forceinline__ void ldm_x4(uint32_t* d, uint32_t addr) {
    asm volatile("ldmatrix.sync.aligned.m8n8.x4.shared.b16 {%0,%1,%2,%3}, [%4];"
                 : "=r"(d[0]), "=r"(d[1]), "=r"(d[2]), "=r"(d[3]) : "r"(addr));
}
__device__ __forceinline__ void ldm_x4_t(uint32_t* d, uint32_t addr) {
    asm volatile("ldmatrix.sync.aligned.m8n8.x4.trans.shared.b16 {%0,%1,%2,%3}, [%4];"
                 : "=r"(d[0]), "=r"(d[1]), "=r"(d[2]), "=r"(d[3]) : "r"(addr));
}
// fp16 mma (all matmuls)
__device__ __forceinline__ void mma16816h(float* c, const uint32_t* a, uint32_t b0, uint32_t b1) {
    asm volatile("mma.sync.aligned.m16n8k16.row.col.f32.f16.f16.f32 "
                 "{%0,%1,%2,%3}, {%4,%5,%6,%7}, {%8,%9}, {%0,%1,%2,%3};"
                 : "+f"(c[0]), "+f"(c[1]), "+f"(c[2]), "+f"(c[3])
                 : "r"(a[0]), "r"(a[1]), "r"(a[2]), "r"(a[3]), "r"(b0), "r"(b1));
}
// fp16 hi/lo split of a pair
__device__ __forceinline__ void split2h(float a, float b, uint32_t& hw, uint32_t& lw) {
    __half2 h = __floats2half2_rn(a, b);
    hw = *reinterpret_cast<uint32_t*>(&h);
    float ha = __half2float(__low2half(h));
    float hb = __half2float(__high2half(h));
    __half2 l = __floats2half2_rn(a - ha, b - hb);
    lw = *reinterpret_cast<uint32_t*>(&l);
}
__device__ __forceinline__ uint32_t pack_h2(float a, float b) {
    __half2 h = __floats2half2_rn(a, b);
    return *reinterpret_cast<uint32_t*>(&h);
}
// swizzle for 32-col (64B-row) 16-bit tiles
__device__ __forceinline__ uint32_t tile_off(int r, int c) {
    return (uint32_t)(r * 64 + ((c ^ ((r >> 1) & 3)) << 4));
}
// swizzle for 64-col (128B-row) 16-bit tiles
__device__ __forceinline__ uint32_t toff128(int r, int c) {
    return (uint32_t)(r * 128 + ((c ^ (r & 7)) << 4));
}

// ---------------------------------------------------------------------------
// splits (fp16 outputs)
// ---------------------------------------------------------------------------
__global__ __launch_bounds__(256) void split_fp32(
    const float* __restrict__ x, __half* __restrict__ hi,
    __half* __restrict__ lo, int n4)
{
    int i = blockIdx.x * 256 + threadIdx.x;
    if (i >= n4) return;
    float4 v = ((const float4*)x)[i];
    uint32_t h0, l0, h1, l1;
    split2h(v.x, v.y, h0, l0);
    split2h(v.z, v.w, h1, l1);
    ((uint2*)hi)[i] = make_uint2(h0, h1);
    ((uint2*)lo)[i] = make_uint2(l0, l1);
}

struct SplitJobs {
    const float* src[4];
    __half* hi[4];
    __half* lo[4];
};
__global__ __launch_bounds__(256) void split_weights(SplitJobs jobs, int n4)
{
    int i = blockIdx.x * 256 + threadIdx.x;
    if (i >= n4) return;
    const int w = blockIdx.y;
    float4 v = ((const float4*)jobs.src[w])[i];
    uint32_t h0, l0, h1, l1;
    split2h(v.x, v.y, h0, l0);
    split2h(v.z, v.w, h1, l1);
    ((uint2*)jobs.hi[w])[i] = make_uint2(h0, h1);
    ((uint2*)jobs.lo[w])[i] = make_uint2(l0, l1);
}

// ---------------------------------------------------------------------------
// fp16 split GEMM: CTA 128x128, warp 32x64, BK=32, 3 stages, 2 CTAs/SM.
// nt=3 (Q,K): Ahi*Whi + Alo*Whi + Ahi*Wlo (err~2^-22)
// nt=2 (V,O): Ahi*Whi + Alo*Whi = A*W_f16  (err~2^-12)
// Output modes: Ohi&&Olo -> fp16 split; Ohi only -> plain fp16; else fp32 C.
// ---------------------------------------------------------------------------
#define GSTAGE 32768
#define SMEM_GEMM (3 * GSTAGE)
#define NCH32 (E_ / 32)

struct GemmJobs {
    const __half* Whi[3];
    const __half* Wlo[3];
    const float* bias[3];
    __half* Ohi[3];
    __half* Olo[3];
    float* C[3];
    float alpha[3];
    int nt[3];
};

__global__ __launch_bounds__(256, 2) void gemm_tc(
    const __half* __restrict__ Ahi, const __half* __restrict__ Alo,
    GemmJobs jobs)
{
    extern __shared__ __align__(1024) char smem[];
    const uint32_t su = smem_u32(smem);
    const int tid = threadIdx.x, wid = tid >> 5, lane = tid & 31;
    const int brow = blockIdx.y * 128, bcol = blockIdx.x * 128;
    const int jz = blockIdx.z;
    const __half* Whi = jobs.Whi[jz];
    const __half* Wlo = jobs.Wlo[jz];
    const bool nt3 = (jobs.nt[jz] == 3);
    const int wm = wid & 3;
    const int wn = wid >> 2;

    float acc[2][8][4];
#pragma unroll
    for (int mt = 0; mt < 2; mt++)
#pragma unroll
        for (int j = 0; j < 8; j++)
#pragma unroll
            for (int q = 0; q < 4; q++) acc[mt][j][q] = 0.f;

    auto load_part = [&](int k0, int s, int p) {
        const uint32_t base = su + s * GSTAGE;
        int idx = tid + p * 256;
        int r = idx >> 2, c = idx & 3;
        uint32_t off = tile_off(r, c);
        size_t ga = (size_t)(brow + r) * E_ + k0 + c * 8;
        size_t gw = (size_t)(bcol + r) * E_ + k0 + c * 8;
        cp16(base +         off, Ahi + ga);
        cp16(base +  8192 + off, Alo + ga);
        cp16(base + 16384 + off, Whi + gw);
        if (nt3) cp16(base + 24576 + off, Wlo + gw);
    };
    auto load_chunk = [&](int k0, int s) {
#pragma unroll
        for (int p = 0; p < 2; p++) load_part(k0, s, p);
        cp_commit();
    };

    load_chunk(0, 0);
    load_chunk(32, 1);

    for (int k = 0; k < NCH32; k++) {
        if (k + 1 < NCH32) { cp_wait<1>(); } else { cp_wait<0>(); }
        __syncthreads();
        const bool pre = (k + 2 < NCH32);
        const int ps = (k + 2) % 3;
        const int pk = (k + 2) * 32;

        const uint32_t bA_hi = su + (k % 3) * GSTAGE;
        const uint32_t bA_lo = bA_hi + 8192;
        const uint32_t bW_hi = bA_hi + 16384;
        const uint32_t bW_lo = bA_hi + 24576;

#pragma unroll
        for (int ks = 0; ks < 2; ks++) {
            if (pre) load_part(pk, ps, ks);
            const int cc = ks * 2 + (lane >> 4);
            uint32_t ah[2][4], al[2][4];
#pragma unroll
            for (int mt = 0; mt < 2; mt++) {
                const uint32_t off = tile_off(wm * 32 + mt * 16 + (lane & 15), cc);
                ldm_x4(ah[mt], bA_hi + off);
                ldm_x4(al[mt], bA_lo + off);
            }
            uint32_t bh[4][4];
#pragma unroll
            for (int nb = 0; nb < 4; nb++) {
                const uint32_t off = tile_off(wn * 64 + nb * 16 + (lane & 15), cc);
                ldm_x4(bh[nb], bW_hi + off);
            }
#pragma unroll
            for (int mt = 0; mt < 2; mt++)
#pragma unroll
                for (int j = 0; j < 8; j++) {
                    const int nb = j >> 1, sel = j & 1;
                    mma16816h(acc[mt][j], ah[mt], bh[nb][sel], bh[nb][sel + 2]);
                }
#pragma unroll
            for (int mt = 0; mt < 2; mt++)
#pragma unroll
                for (int j = 0; j < 8; j++) {
                    const int nb = j >> 1, sel = j & 1;
                    mma16816h(acc[mt][j], al[mt], bh[nb][sel], bh[nb][sel + 2]);
                }
            if (nt3) {
                uint32_t bl[4][4];
#pragma unroll
                for (int nb = 0; nb < 4; nb++) {
                    const uint32_t off = tile_off(wn * 64 + nb * 16 + (lane & 15), cc);
                    ldm_x4(bl[nb], bW_lo + off);
                }
#pragma unroll
                for (int mt = 0; mt < 2; mt++)
#pragma unroll
                    for (int j = 0; j < 8; j++) {
                        const int nb = j >> 1, sel = j & 1;
                        mma16816h(acc[mt][j], ah[mt], bl[nb][sel], bl[nb][sel + 2]);
                    }
            }
        }
        if (pre) cp_commit();
    }

    const float alpha = jobs.alpha[jz];
    const float* bias = jobs.bias[jz];
    __half* Ohi = jobs.Ohi[jz];
    __half* Olo = jobs.Olo[jz];
    float* C = jobs.C[jz];
#pragma unroll
    for (int mt = 0; mt < 2; mt++) {
        const int r0 = brow + wm * 32 + mt * 16 + (lane >> 2);
#pragma unroll
        for (int j = 0; j < 8; j++) {
            const int col = bcol + wn * 64 + j * 8 + (lane & 3) * 2;
            const float bx = bias[col], by = bias[col + 1];
            float v00 = alpha * (acc[mt][j][0] + bx);
            float v01 = alpha * (acc[mt][j][1] + by);
            float v10 = alpha * (acc[mt][j][2] + bx);
            float v11 = alpha * (acc[mt][j][3] + by);
            if (Ohi && Olo) {        // Q,K: fp16 split
                uint32_t hw, lw;
                split2h(v00, v01, hw, lw);
                *(uint32_t*)&Ohi[(size_t)r0 * E_ + col] = hw;
                *(uint32_t*)&Olo[(size_t)r0 * E_ + col] = lw;
                split2h(v10, v11, hw, lw);
                *(uint32_t*)&Ohi[(size_t)(r0 + 8) * E_ + col] = hw;
                *(uint32_t*)&Olo[(size_t)(r0 + 8) * E_ + col] = lw;
            } else if (Ohi) {        // V: plain fp16
                *(uint32_t*)&Ohi[(size_t)r0 * E_ + col]       = pack_h2(v00, v01);
                *(uint32_t*)&Ohi[(size_t)(r0 + 8) * E_ + col] = pack_h2(v10, v11);
            } else {                 // O-proj: fp32 final output
                *(float2*)&C[(size_t)r0 * E_ + col]       = make_float2(v00, v01);
                *(float2*)&C[(size_t)(r0 + 8) * E_ + col] = make_float2(v10, v11);
            }
        }
    }
}

// ---------------------------------------------------------------------------
// fp16 flash attention: QK^T 3-pass fp16-split; PV 2-pass (split P x plain V).
// smem: Qhi 8K | Qlo 8K | 2 stages x (Khi 8K | Klo 8K | V 8K) = 64KB
// ---------------------------------------------------------------------------
#define AT_STAGE 24576
#define SMEM_ATTN (16384 + 2 * AT_STAGE)

__global__ __launch_bounds__(128, 1) void attn_tc(
    const __half* __restrict__ Qhi, const __half* __restrict__ Qlo,
    const __half* __restrict__ Khi, const __half* __restrict__ Klo,
    const __half* __restrict__ V,
    __half* __restrict__ Chi, __half* __restrict__ Clo)
{
    extern __shared__ __align__(1024) char smem[];
    const uint32_t su = smem_u32(smem);
    const int tid = threadIdx.x, w = tid >> 5, lane = tid & 31;
    const int qt = gridDim.x - 1 - blockIdx.x;
    const int bh = blockIdx.y;
    const int b = bh >> 5, h = bh & 31;

    const size_t rowQ0 = (size_t)(b * T_ + qt * 64);
    const size_t rowK0 = (size_t)(b * T_);
    const int hoff = h * 64;

    auto load_q = [&]() {
#pragma unroll
        for (int it = 0; it < 4; it++) {
            int idx = tid + it * 128;
            int r = idx >> 3, c = idx & 7;
            uint32_t off = toff128(r, c);
            size_t g = (rowQ0 + r) * E_ + hoff + c * 8;
            cp16(su +        off, Qhi + g);
            cp16(su + 8192 + off, Qlo + g);
        }
    };
    auto load_kv = [&](int jt, int s) {
        const uint32_t base = su + 16384 + s * AT_STAGE;
#pragma unroll
        for (int it = 0; it < 4; it++) {
            int idx = tid + it * 128;
            int r = idx >> 3, c = idx & 7;
            uint32_t off = toff128(r, c);
            size_t g = (rowK0 + jt * 64 + r) * E_ + hoff + c * 8;
            cp16(base +         off, Khi + g);
            cp16(base +  8192 + off, Klo + g);
            cp16(base + 16384 + off, V + g);
        }
    };

    load_q();
    load_kv(0, 0);
    cp_commit();
    cp_wait<0>();
    __syncthreads();

    uint32_t qh[4][4], ql[4][4];
#pragma unroll
    for (int ks = 0; ks < 4; ks++) {
        const uint32_t off = toff128(16 * w + (lane & 15), ks * 2 + (lane >> 4));
        ldm_x4(qh[ks], su + off);
        ldm_x4(ql[ks], su + 8192 + off);
    }

    float oc[8][4];
#pragma unroll
    for (int nb = 0; nb < 8; nb++)
#pragma unroll
        for (int q = 0; q < 4; q++) oc[nb][q] = 0.f;
    float mrow0 = -CUDART_INF_F, mrow1 = -CUDART_INF_F;
    float lrow0 = 0.f, lrow1 = 0.f;

    for (int jt = 0; jt <= qt; jt++) {
        const int s = jt & 1;
        if (jt + 1 <= qt) {
            load_kv(jt + 1, s ^ 1);
            cp_commit();
            cp_wait<1>();
        } else {
            cp_wait<0>();
        }
        __syncthreads();

        const uint32_t bK_hi = su + 16384 + s * AT_STAGE;
        const uint32_t bK_lo = bK_hi + 8192;
        const uint32_t bV    = bK_hi + 16384;

        float sc[8][4];
#pragma unroll
        for (int nb = 0; nb < 8; nb++)
#pragma unroll
            for (int q = 0; q < 4; q++) sc[nb][q] = 0.f;
#pragma unroll
        for (int ks = 0; ks < 4; ks++) {
            const int cc = ks * 2 + (lane >> 4);
            uint32_t kh[4][4], kl[4][4];
#pragma unroll
            for (int nbp = 0; nbp < 4; nbp++) {
                const uint32_t off = toff128(nbp * 16 + (lane & 15), cc);
                ldm_x4(kh[nbp], bK_hi + off);
                ldm_x4(kl[nbp], bK_lo + off);
            }
#pragma unroll
            for (int nbp = 0; nbp < 4; nbp++) {
                mma16816h(sc[2 * nbp],     qh[ks], kh[nbp][0], kh[nbp][2]);
                mma16816h(sc[2 * nbp + 1], qh[ks], kh[nbp][1], kh[nbp][3]);
            }
#pragma unroll
            for (int nbp = 0; nbp < 4; nbp++) {
                mma16816h(sc[2 * nbp],     qh[ks], kl[nbp][0], kl[nbp][2]);
                mma16816h(sc[2 * nbp + 1], qh[ks], kl[nbp][1], kl[nbp][3]);
            }
#pragma unroll
            for (int nbp = 0; nbp < 4; nbp++) {
                mma16816h(sc[2 * nbp],     ql[ks], kh[nbp][0], kh[nbp][2]);
                mma16816h(sc[2 * nbp + 1], ql[ks], kh[nbp][1], kh[nbp][3]);
            }
        }

        if (jt == qt) {
            const int r0 = 16 * w + (lane >> 2);
#pragma unroll
            for (int nb = 0; nb < 8; nb++) {
                const int c0 = 8 * nb + 2 * (lane & 3);
                if (c0 > r0)     sc[nb][0] = -CUDART_INF_F;
                if (c0 + 1 > r0) sc[nb][1] = -CUDART_INF_F;
                if (c0 > r0 + 8)     sc[nb][2] = -CUDART_INF_F;
                if (c0 + 1 > r0 + 8) sc[nb][3] = -CUDART_INF_F;
            }
        }

        float tm0 = -CUDART_INF_F, tm1 = -CUDART_INF_F;
#pragma unroll
        for (int nb = 0; nb < 8; nb++) {
            tm0 = fmaxf(tm0, fmaxf(sc[nb][0], sc[nb][1]));
            tm1 = fmaxf(tm1, fmaxf(sc[nb][2], sc[nb][3]));
        }
        tm0 = fmaxf(tm0, __shfl_xor_sync(0xffffffffu, tm0, 1));
        tm0 = fmaxf(tm0, __shfl_xor_sync(0xffffffffu, tm0, 2));
        tm1 = fmaxf(tm1, __shfl_xor_sync(0xffffffffu, tm1, 1));
        tm1 = fmaxf(tm1, __shfl_xor_sync(0xffffffffu, tm1, 2));
        const float mn0 = fmaxf(mrow0, tm0), mn1 = fmaxf(mrow1, tm1);
        const float scl0 = __expf(mrow0 - mn0), scl1 = __expf(mrow1 - mn1);
        float ls0 = 0.f, ls1 = 0.f;
#pragma unroll
        for (int nb = 0; nb < 8; nb++) {
            sc[nb][0] = __expf(sc[nb][0] - mn0);
            sc[nb][1] = __expf(sc[nb][1] - mn0);
            sc[nb][2] = __expf(sc[nb][2] - mn1);
            sc[nb][3] = __expf(sc[nb][3] - mn1);
            ls0 += sc[nb][0] + sc[nb][1];
            ls1 += sc[nb][2] + sc[nb][3];
        }
        ls0 += __shfl_xor_sync(0xffffffffu, ls0, 1);
        ls0 += __shfl_xor_sync(0xffffffffu, ls0, 2);
        ls1 += __shfl_xor_sync(0xffffffffu, ls1, 1);
        ls1 += __shfl_xor_sync(0xffffffffu, ls1, 2);
        lrow0 = lrow0 * scl0 + ls0;
        lrow1 = lrow1 * scl1 + ls1;
        mrow0 = mn0; mrow1 = mn1;
#pragma unroll
        for (int nb = 0; nb < 8; nb++) {
            oc[nb][0] *= scl0; oc[nb][1] *= scl0;
            oc[nb][2] *= scl1; oc[nb][3] *= scl1;
        }

        // repack P into fp16-split A-fragments
        uint32_t aph[4][4], apl[4][4];
#pragma unroll
        for (int ks = 0; ks < 4; ks++) {
            split2h(sc[2 * ks][0],     sc[2 * ks][1],     aph[ks][0], apl[ks][0]);
            split2h(sc[2 * ks][2],     sc[2 * ks][3],     aph[ks][1], apl[ks][1]);
            split2h(sc[2 * ks + 1][0], sc[2 * ks + 1][1], aph[ks][2], apl[ks][2]);
            split2h(sc[2 * ks + 1][2], sc[2 * ks + 1][3], aph[ks][3], apl[ks][3]);
        }

        // O += P V : 2-pass (Phi + Plo) x plain-V
#pragma unroll
        for (int ks = 0; ks < 4; ks++) {
            uint32_t vh[4][4];
#pragma unroll
            for (int dbp = 0; dbp < 4; dbp++) {
                const uint32_t off = toff128(16 * ks + (lane & 15), dbp * 2 + (lane >> 4));
                ldm_x4_t(vh[dbp], bV + off);
            }
#pragma unroll
            for (int dbp = 0; dbp < 4; dbp++) {
                mma16816h(oc[2 * dbp],     aph[ks], vh[dbp][0], vh[dbp][1]);
                mma16816h(oc[2 * dbp + 1], aph[ks], vh[dbp][2], vh[dbp][3]);
            }
#pragma unroll
            for (int dbp = 0; dbp < 4; dbp++) {
                mma16816h(oc[2 * dbp],     apl[ks], vh[dbp][0], vh[dbp][1]);
                mma16816h(oc[2 * dbp + 1], apl[ks], vh[dbp][2], vh[dbp][3]);
            }
        }
        __syncthreads();
    }

    // epilogue: ctx = O / l -> fp16 split
    const float inv0 = 1.f / lrow0, inv1 = 1.f / lrow1;
    const size_t r0 = rowQ0 + 16 * w + (lane >> 2);
#pragma unroll
    for (int nb = 0; nb < 8; nb++) {
        const int col = hoff + 8 * nb + 2 * (lane & 3);
        uint32_t hw, lw;
        split2h(oc[nb][0] * inv0, oc[nb][1] * inv0, hw, lw);
        *(uint32_t*)&Chi[r0 * E_ + col] = hw;
        *(uint32_t*)&Clo[r0 * E_ + col] = lw;
        split2h(oc[nb][2] * inv1, oc[nb][3] * inv1, hw, lw);
        *(uint32_t*)&Chi[(r0 + 8) * E_ + col] = hw;
        *(uint32_t*)&Clo[(r0 + 8) * E_ + col] = lw;
    }
}

// ---------------------------------------------------------------------------
extern "C" void kernel_launch(void* const* d_in, const int* in_sizes, int n_in,
                              void* d_out, int out_size)
{
    const float* X  = (const float*)d_in[0];
    const float* Wq = (const float*)d_in[1];
    const float* bq = (const float*)d_in[2];
    const float* Wk = (const float*)d_in[3];
    const float* bk = (const float*)d_in[4];
    const float* Wv = (const float*)d_in[5];
    const float* bv = (const float*)d_in[6];
    const float* Wo = (const float*)d_in[7];
    const float* bo = (const float*)d_in[8];
    float* out = (float*)d_out;

    __half *Ahi, *Alo, *WhiB, *WloB, *Qhi, *Qlo, *Khi, *Klo, *Vp;
    cudaGetSymbolAddress((void**)&Ahi, g_Ahi);
    cudaGetSymbolAddress((void**)&Alo, g_Alo);
    cudaGetSymbolAddress((void**)&WhiB, g_Whi);
    cudaGetSymbolAddress((void**)&WloB, g_Wlo);
    cudaGetSymbolAddress((void**)&Qhi, g_Qhi);
    cudaGetSymbolAddress((void**)&Qlo, g_Qlo);
    cudaGetSymbolAddress((void**)&Khi, g_Khi);
    cudaGetSymbolAddress((void**)&Klo, g_Klo);
    cudaGetSymbolAddress((void**)&Vp, g_V);
    const size_t WSZ = (size_t)E_ * E_;

    cudaFuncSetAttribute(gemm_tc, cudaFuncAttributeMaxDynamicSharedMemorySize, SMEM_GEMM);
    cudaFuncSetAttribute(attn_tc, cudaFuncAttributeMaxDynamicSharedMemorySize, SMEM_ATTN);

    const int nX4 = (M_ * E_) / 4;
    const int nW4 = (E_ * E_) / 4;

    SplitJobs sj;
    sj.src[0] = Wq; sj.src[1] = Wk; sj.src[2] = Wv; sj.src[3] = Wo;
    for (int i = 0; i < 4; i++) { sj.hi[i] = WhiB + i * WSZ; sj.lo[i] = WloB + i * WSZ; }
    split_weights<<<dim3((nW4 + 255) / 256, 4), 256>>>(sj, nW4);
    split_fp32<<<(nX4 + 255) / 256, 256>>>(X, Ahi, Alo, nX4);

    // batched Q,K,V projections (Q,K: 3-pass split-out; V: 2-pass plain fp16)
    GemmJobs qkv;
    qkv.Whi[0] = WhiB;           qkv.Wlo[0] = WloB;
    qkv.Whi[1] = WhiB + WSZ;     qkv.Wlo[1] = WloB + WSZ;
    qkv.Whi[2] = WhiB + 2 * WSZ; qkv.Wlo[2] = WloB + 2 * WSZ;
    qkv.bias[0] = bq; qkv.bias[1] = bk; qkv.bias[2] = bv;
    qkv.Ohi[0] = Qhi; qkv.Olo[0] = Qlo;
    qkv.Ohi[1] = Khi; qkv.Olo[1] = Klo;
    qkv.Ohi[2] = Vp;  qkv.Olo[2] = nullptr;
    qkv.C[0] = qkv.C[1] = qkv.C[2] = nullptr;
    qkv.alpha[0] = SCALING; qkv.alpha[1] = 1.f; qkv.alpha[2] = 1.f;
    qkv.nt[0] = 3; qkv.nt[1] = 3; qkv.nt[2] = 2;
    gemm_tc<<<dim3(E_ / 128, M_ / 128, 3), 256, SMEM_GEMM>>>(Ahi, Alo, qkv);

    dim3 ag(T_ / 64, B_ * H_);
    attn_tc<<<ag, 128, SMEM_ATTN>>>(Qhi, Qlo, Khi, Klo, Vp, Ahi, Alo);

    // output projection (2-pass, fp32 out)
    GemmJobs oj;
    oj.Whi[0] = WhiB + 3 * WSZ; oj.Wlo[0] = WloB + 3 * WSZ;
    oj.bias[0] = bo;
    oj.Ohi[0] = nullptr; oj.Olo[0] = nullptr;
    oj.C[0] = out;
    oj.alpha[0] = 1.f;
    oj.nt[0] = 2;
    oj.Whi[1] = oj.Whi[2] = nullptr; oj.Wlo[1] = oj.Wlo[2] = nullptr;
    oj.bias[1] = oj.bias[2] = nullptr;
    oj.Ohi[1] = oj.Ohi[2] = nullptr; oj.Olo[1] = oj.Olo[2] = nullptr;
    oj.C[1] = oj.C[2] = nullptr;
    oj.alpha[1] = oj.alpha[2] = 0.f;
    oj.nt[1] = oj.nt[2] = 2;
    gemm_tc<<<dim3(E_ / 128, M_ / 128, 1), 256, SMEM_GEMM>>>(Ahi, Alo, oj);
}

// round 17
// speedup vs baseline: 1.1804x; 1.0333x over previous
#include <cuda_runtime.h>
#include <cuda_fp16.h>
#include <math_constants.h>
#include <cstdint>

#define B_ 2
#define T_ 2048
#define E_ 2048
#define H_ 32
#define D_ 64
#define M_ (B_ * T_)
#define SCALING 0.125f
#define LOG2E 1.44269504088896f

// ---------------- scratch (__device__ globals; allocation-free rule) --------
__device__ __half g_Ahi[M_ * E_];          // fp16 split of X; later ctx
__device__ __half g_Alo[M_ * E_];
__device__ __half g_Whi[4][E_ * E_];       // q,k,v,o weight fp16 splits
__device__ __half g_Wlo[4][E_ * E_];
__device__ __half g_Qhi[M_ * E_];          // fp16-split Q,K; plain fp16 V
__device__ __half g_Qlo[M_ * E_];
__device__ __half g_Khi[M_ * E_];
__device__ __half g_Klo[M_ * E_];
__device__ __half g_V[M_ * E_];

// ---------------- helpers ---------------------------------------------------
__device__ __forceinline__ uint32_t smem_u32(const void* p) {
    uint32_t a;
    asm("{ .reg .u64 t; cvta.to.shared.u64 t, %1; cvt.u32.u64 %0, t; }" : "=r"(a) : "l"(p));
    return a;
}
__device__ __forceinline__ void cp16(uint32_t dst, const void* src) {
    asm volatile("cp.async.cg.shared.global [%0], [%1], 16;" :: "r"(dst), "l"(src));
}
__device__ __forceinline__ void cp_commit() {
    asm volatile("cp.async.commit_group;" ::: "memory");
}
template <int N>
__device__ __forceinline__ void cp_wait() {
    asm volatile("cp.async.wait_group %0;" :: "n"(N) : "memory");
}
__device__ __forceinline__ void ldm_x4(uint32_t* d, uint32_t addr) {
    asm volatile("ldmatrix.sync.aligned.m8n8.x4.shared.b16 {%0,%1,%2,%3}, [%4];"
                 : "=r"(d[0]), "=r"(d[1]), "=r"(d[2]), "=r"(d[3]) : "r"(addr));
}
__device__ __forceinline__ void ldm_x4_t(uint32_t* d, uint32_t addr) {
    asm volatile("ldmatrix.sync.aligned.m8n8.x4.trans.shared.b16 {%0,%1,%2,%3}, [%4];"
                 : "=r"(d[0]), "=r"(d[1]), "=r"(d[2]), "=r"(d[3]) : "r"(addr));
}
// fp16 mma (all matmuls)
__device__ __forceinline__ void mma16816h(float* c, const uint32_t* a, uint32_t b0, uint32_t b1) {
    asm volatile("mma.sync.aligned.m16n8k16.row.col.f32.f16.f16.f32 "
                 "{%0,%1,%2,%3}, {%4,%5,%6,%7}, {%8,%9}, {%0,%1,%2,%3};"
                 : "+f"(c[0]), "+f"(c[1]), "+f"(c[2]), "+f"(c[3])
                 : "r"(a[0]), "r"(a[1]), "r"(a[2]), "r"(a[3]), "r"(b0), "r"(b1));
}
// fp16 hi/lo split of a pair
__device__ __forceinline__ void split2h(float a, float b, uint32_t& hw, uint32_t& lw) {
    __half2 h = __floats2half2_rn(a, b);
    hw = *reinterpret_cast<uint32_t*>(&h);
    float ha = __half2float(__low2half(h));
    float hb = __half2float(__high2half(h));
    __half2 l = __floats2half2_rn(a - ha, b - hb);
    lw = *reinterpret_cast<uint32_t*>(&l);
}
__device__ __forceinline__ uint32_t pack_h2(float a, float b) {
    __half2 h = __floats2half2_rn(a, b);
    return *reinterpret_cast<uint32_t*>(&h);
}
// swizzle for 32-col (64B-row) 16-bit tiles
__device__ __forceinline__ uint32_t tile_off(int r, int c) {
    return (uint32_t)(r * 64 + ((c ^ ((r >> 1) & 3)) << 4));
}
// swizzle for 64-col (128B-row) 16-bit tiles
__device__ __forceinline__ uint32_t toff128(int r, int c) {
    return (uint32_t)(r * 128 + ((c ^ (r & 7)) << 4));
}

// ---------------------------------------------------------------------------
// splits (fp16 outputs)
// ---------------------------------------------------------------------------
__global__ __launch_bounds__(256) void split_fp32(
    const float* __restrict__ x, __half* __restrict__ hi,
    __half* __restrict__ lo, int n4)
{
    int i = blockIdx.x * 256 + threadIdx.x;
    if (i >= n4) return;
    float4 v = ((const float4*)x)[i];
    uint32_t h0, l0, h1, l1;
    split2h(v.x, v.y, h0, l0);
    split2h(v.z, v.w, h1, l1);
    ((uint2*)hi)[i] = make_uint2(h0, h1);
    ((uint2*)lo)[i] = make_uint2(l0, l1);
}

struct SplitJobs {
    const float* src[4];
    __half* hi[4];
    __half* lo[4];
};
__global__ __launch_bounds__(256) void split_weights(SplitJobs jobs, int n4)
{
    int i = blockIdx.x * 256 + threadIdx.x;
    if (i >= n4) return;
    const int w = blockIdx.y;
    float4 v = ((const float4*)jobs.src[w])[i];
    uint32_t h0, l0, h1, l1;
    split2h(v.x, v.y, h0, l0);
    split2h(v.z, v.w, h1, l1);
    ((uint2*)jobs.hi[w])[i] = make_uint2(h0, h1);
    ((uint2*)jobs.lo[w])[i] = make_uint2(l0, l1);
}

// ---------------------------------------------------------------------------
// fp16 split GEMM: CTA 128x128, warp 32x64, BK=32, 3 stages, 2 CTAs/SM.
// nt=3 (Q,K): Ahi*Whi + Alo*Whi + Ahi*Wlo (err~2^-22)
// nt=2 (V,O): Ahi*Whi + Alo*Whi = A*W_f16  (err~2^-12)
// Output modes: Ohi&&Olo -> fp16 split; Ohi only -> plain fp16; else fp32 C.
// ---------------------------------------------------------------------------
#define GSTAGE 32768
#define SMEM_GEMM (3 * GSTAGE)
#define NCH32 (E_ / 32)

struct GemmJobs {
    const __half* Whi[3];
    const __half* Wlo[3];
    const float* bias[3];
    __half* Ohi[3];
    __half* Olo[3];
    float* C[3];
    float alpha[3];
    int nt[3];
};

__global__ __launch_bounds__(256, 2) void gemm_tc(
    const __half* __restrict__ Ahi, const __half* __restrict__ Alo,
    GemmJobs jobs)
{
    extern __shared__ __align__(1024) char smem[];
    const uint32_t su = smem_u32(smem);
    const int tid = threadIdx.x, wid = tid >> 5, lane = tid & 31;
    const int brow = blockIdx.y * 128, bcol = blockIdx.x * 128;
    const int jz = blockIdx.z;
    const __half* Whi = jobs.Whi[jz];
    const __half* Wlo = jobs.Wlo[jz];
    const bool nt3 = (jobs.nt[jz] == 3);
    const int wm = wid & 3;
    const int wn = wid >> 2;

    float acc[2][8][4];
#pragma unroll
    for (int mt = 0; mt < 2; mt++)
#pragma unroll
        for (int j = 0; j < 8; j++)
#pragma unroll
            for (int q = 0; q < 4; q++) acc[mt][j][q] = 0.f;

    auto load_part = [&](int k0, int s, int p) {
        const uint32_t base = su + s * GSTAGE;
        int idx = tid + p * 256;
        int r = idx >> 2, c = idx & 3;
        uint32_t off = tile_off(r, c);
        size_t ga = (size_t)(brow + r) * E_ + k0 + c * 8;
        size_t gw = (size_t)(bcol + r) * E_ + k0 + c * 8;
        cp16(base +         off, Ahi + ga);
        cp16(base +  8192 + off, Alo + ga);
        cp16(base + 16384 + off, Whi + gw);
        if (nt3) cp16(base + 24576 + off, Wlo + gw);
    };
    auto load_chunk = [&](int k0, int s) {
#pragma unroll
        for (int p = 0; p < 2; p++) load_part(k0, s, p);
        cp_commit();
    };

    load_chunk(0, 0);
    load_chunk(32, 1);

    for (int k = 0; k < NCH32; k++) {
        if (k + 1 < NCH32) { cp_wait<1>(); } else { cp_wait<0>(); }
        __syncthreads();
        const bool pre = (k + 2 < NCH32);
        const int ps = (k + 2) % 3;
        const int pk = (k + 2) * 32;

        const uint32_t bA_hi = su + (k % 3) * GSTAGE;
        const uint32_t bA_lo = bA_hi + 8192;
        const uint32_t bW_hi = bA_hi + 16384;
        const uint32_t bW_lo = bA_hi + 24576;

#pragma unroll
        for (int ks = 0; ks < 2; ks++) {
            if (pre) load_part(pk, ps, ks);
            const int cc = ks * 2 + (lane >> 4);
            uint32_t ah[2][4], al[2][4];
#pragma unroll
            for (int mt = 0; mt < 2; mt++) {
                const uint32_t off = tile_off(wm * 32 + mt * 16 + (lane & 15), cc);
                ldm_x4(ah[mt], bA_hi + off);
                ldm_x4(al[mt], bA_lo + off);
            }
            uint32_t bh[4][4];
#pragma unroll
            for (int nb = 0; nb < 4; nb++) {
                const uint32_t off = tile_off(wn * 64 + nb * 16 + (lane & 15), cc);
                ldm_x4(bh[nb], bW_hi + off);
            }
#pragma unroll
            for (int mt = 0; mt < 2; mt++)
#pragma unroll
                for (int j = 0; j < 8; j++) {
                    const int nb = j >> 1, sel = j & 1;
                    mma16816h(acc[mt][j], ah[mt], bh[nb][sel], bh[nb][sel + 2]);
                }
#pragma unroll
            for (int mt = 0; mt < 2; mt++)
#pragma unroll
                for (int j = 0; j < 8; j++) {
                    const int nb = j >> 1, sel = j & 1;
                    mma16816h(acc[mt][j], al[mt], bh[nb][sel], bh[nb][sel + 2]);
                }
            if (nt3) {
                uint32_t bl[4][4];
#pragma unroll
                for (int nb = 0; nb < 4; nb++) {
                    const uint32_t off = tile_off(wn * 64 + nb * 16 + (lane & 15), cc);
                    ldm_x4(bl[nb], bW_lo + off);
                }
#pragma unroll
                for (int mt = 0; mt < 2; mt++)
#pragma unroll
                    for (int j = 0; j < 8; j++) {
                        const int nb = j >> 1, sel = j & 1;
                        mma16816h(acc[mt][j], ah[mt], bl[nb][sel], bl[nb][sel + 2]);
                    }
            }
        }
        if (pre) cp_commit();
    }

    const float alpha = jobs.alpha[jz];
    const float* bias = jobs.bias[jz];
    __half* Ohi = jobs.Ohi[jz];
    __half* Olo = jobs.Olo[jz];
    float* C = jobs.C[jz];
#pragma unroll
    for (int mt = 0; mt < 2; mt++) {
        const int r0 = brow + wm * 32 + mt * 16 + (lane >> 2);
#pragma unroll
        for (int j = 0; j < 8; j++) {
            const int col = bcol + wn * 64 + j * 8 + (lane & 3) * 2;
            const float bx = bias[col], by = bias[col + 1];
            float v00 = alpha * (acc[mt][j][0] + bx);
            float v01 = alpha * (acc[mt][j][1] + by);
            float v10 = alpha * (acc[mt][j][2] + bx);
            float v11 = alpha * (acc[mt][j][3] + by);
            if (Ohi && Olo) {        // Q,K: fp16 split
                uint32_t hw, lw;
                split2h(v00, v01, hw, lw);
                *(uint32_t*)&Ohi[(size_t)r0 * E_ + col] = hw;
                *(uint32_t*)&Olo[(size_t)r0 * E_ + col] = lw;
                split2h(v10, v11, hw, lw);
                *(uint32_t*)&Ohi[(size_t)(r0 + 8) * E_ + col] = hw;
                *(uint32_t*)&Olo[(size_t)(r0 + 8) * E_ + col] = lw;
            } else if (Ohi) {        // V: plain fp16
                *(uint32_t*)&Ohi[(size_t)r0 * E_ + col]       = pack_h2(v00, v01);
                *(uint32_t*)&Ohi[(size_t)(r0 + 8) * E_ + col] = pack_h2(v10, v11);
            } else {                 // O-proj: fp32 final output
                *(float2*)&C[(size_t)r0 * E_ + col]       = make_float2(v00, v01);
                *(float2*)&C[(size_t)(r0 + 8) * E_ + col] = make_float2(v10, v11);
            }
        }
    }
}

// ---------------------------------------------------------------------------
// fp16 flash attention: QK^T 3-pass fp16-split; PV 1-pass (plain-fp16 P x V).
// Scores arrive pre-scaled by log2(e) -> exp2-domain softmax.
// smem: Qhi 8K | Qlo 8K | 2 stages x (Khi 8K | Klo 8K | V 8K) = 64KB
// ---------------------------------------------------------------------------
#define AT_STAGE 24576
#define SMEM_ATTN (16384 + 2 * AT_STAGE)

__global__ __launch_bounds__(128, 1) void attn_tc(
    const __half* __restrict__ Qhi, const __half* __restrict__ Qlo,
    const __half* __restrict__ Khi, const __half* __restrict__ Klo,
    const __half* __restrict__ V,
    __half* __restrict__ Chi, __half* __restrict__ Clo)
{
    extern __shared__ __align__(1024) char smem[];
    const uint32_t su = smem_u32(smem);
    const int tid = threadIdx.x, w = tid >> 5, lane = tid & 31;
    const int qt = gridDim.x - 1 - blockIdx.x;
    const int bh = blockIdx.y;
    const int b = bh >> 5, h = bh & 31;

    const size_t rowQ0 = (size_t)(b * T_ + qt * 64);
    const size_t rowK0 = (size_t)(b * T_);
    const int hoff = h * 64;

    auto load_q = [&]() {
#pragma unroll
        for (int it = 0; it < 4; it++) {
            int idx = tid + it * 128;
            int r = idx >> 3, c = idx & 7;
            uint32_t off = toff128(r, c);
            size_t g = (rowQ0 + r) * E_ + hoff + c * 8;
            cp16(su +        off, Qhi + g);
            cp16(su + 8192 + off, Qlo + g);
        }
    };
    auto load_kv = [&](int jt, int s) {
        const uint32_t base = su + 16384 + s * AT_STAGE;
#pragma unroll
        for (int it = 0; it < 4; it++) {
            int idx = tid + it * 128;
            int r = idx >> 3, c = idx & 7;
            uint32_t off = toff128(r, c);
            size_t g = (rowK0 + jt * 64 + r) * E_ + hoff + c * 8;
            cp16(base +         off, Khi + g);
            cp16(base +  8192 + off, Klo + g);
            cp16(base + 16384 + off, V + g);
        }
    };

    load_q();
    load_kv(0, 0);
    cp_commit();
    cp_wait<0>();
    __syncthreads();

    uint32_t qh[4][4], ql[4][4];
#pragma unroll
    for (int ks = 0; ks < 4; ks++) {
        const uint32_t off = toff128(16 * w + (lane & 15), ks * 2 + (lane >> 4));
        ldm_x4(qh[ks], su + off);
        ldm_x4(ql[ks], su + 8192 + off);
    }

    float oc[8][4];
#pragma unroll
    for (int nb = 0; nb < 8; nb++)
#pragma unroll
        for (int q = 0; q < 4; q++) oc[nb][q] = 0.f;
    float mrow0 = -CUDART_INF_F, mrow1 = -CUDART_INF_F;
    float lrow0 = 0.f, lrow1 = 0.f;

    for (int jt = 0; jt <= qt; jt++) {
        const int s = jt & 1;
        if (jt + 1 <= qt) {
            load_kv(jt + 1, s ^ 1);
            cp_commit();
            cp_wait<1>();
        } else {
            cp_wait<0>();
        }
        __syncthreads();

        const uint32_t bK_hi = su + 16384 + s * AT_STAGE;
        const uint32_t bK_lo = bK_hi + 8192;
        const uint32_t bV    = bK_hi + 16384;

        float sc[8][4];
#pragma unroll
        for (int nb = 0; nb < 8; nb++)
#pragma unroll
            for (int q = 0; q < 4; q++) sc[nb][q] = 0.f;
#pragma unroll
        for (int ks = 0; ks < 4; ks++) {
            const int cc = ks * 2 + (lane >> 4);
            uint32_t kh[4][4], kl[4][4];
#pragma unroll
            for (int nbp = 0; nbp < 4; nbp++) {
                const uint32_t off = toff128(nbp * 16 + (lane & 15), cc);
                ldm_x4(kh[nbp], bK_hi + off);
                ldm_x4(kl[nbp], bK_lo + off);
            }
#pragma unroll
            for (int nbp = 0; nbp < 4; nbp++) {
                mma16816h(sc[2 * nbp],     qh[ks], kh[nbp][0], kh[nbp][2]);
                mma16816h(sc[2 * nbp + 1], qh[ks], kh[nbp][1], kh[nbp][3]);
            }
#pragma unroll
            for (int nbp = 0; nbp < 4; nbp++) {
                mma16816h(sc[2 * nbp],     qh[ks], kl[nbp][0], kl[nbp][2]);
                mma16816h(sc[2 * nbp + 1], qh[ks], kl[nbp][1], kl[nbp][3]);
            }
#pragma unroll
            for (int nbp = 0; nbp < 4; nbp++) {
                mma16816h(sc[2 * nbp],     ql[ks], kh[nbp][0], kh[nbp][2]);
                mma16816h(sc[2 * nbp + 1], ql[ks], kh[nbp][1], kh[nbp][3]);
            }
        }

        if (jt == qt) {
            const int r0 = 16 * w + (lane >> 2);
#pragma unroll
            for (int nb = 0; nb < 8; nb++) {
                const int c0 = 8 * nb + 2 * (lane & 3);
                if (c0 > r0)     sc[nb][0] = -CUDART_INF_F;
                if (c0 + 1 > r0) sc[nb][1] = -CUDART_INF_F;
                if (c0 > r0 + 8)     sc[nb][2] = -CUDART_INF_F;
                if (c0 + 1 > r0 + 8) sc[nb][3] = -CUDART_INF_F;
            }
        }

        float tm0 = -CUDART_INF_F, tm1 = -CUDART_INF_F;
#pragma unroll
        for (int nb = 0; nb < 8; nb++) {
            tm0 = fmaxf(tm0, fmaxf(sc[nb][0], sc[nb][1]));
            tm1 = fmaxf(tm1, fmaxf(sc[nb][2], sc[nb][3]));
        }
        tm0 = fmaxf(tm0, __shfl_xor_sync(0xffffffffu, tm0, 1));
        tm0 = fmaxf(tm0, __shfl_xor_sync(0xffffffffu, tm0, 2));
        tm1 = fmaxf(tm1, __shfl_xor_sync(0xffffffffu, tm1, 1));
        tm1 = fmaxf(tm1, __shfl_xor_sync(0xffffffffu, tm1, 2));
        const float mn0 = fmaxf(mrow0, tm0), mn1 = fmaxf(mrow1, tm1);
        const float scl0 = exp2f(mrow0 - mn0), scl1 = exp2f(mrow1 - mn1);
        float ls0 = 0.f, ls1 = 0.f;
#pragma unroll
        for (int nb = 0; nb < 8; nb++) {
            sc[nb][0] = exp2f(sc[nb][0] - mn0);
            sc[nb][1] = exp2f(sc[nb][1] - mn0);
            sc[nb][2] = exp2f(sc[nb][2] - mn1);
            sc[nb][3] = exp2f(sc[nb][3] - mn1);
            ls0 += sc[nb][0] + sc[nb][1];
            ls1 += sc[nb][2] + sc[nb][3];
        }
        ls0 += __shfl_xor_sync(0xffffffffu, ls0, 1);
        ls0 += __shfl_xor_sync(0xffffffffu, ls0, 2);
        ls1 += __shfl_xor_sync(0xffffffffu, ls1, 1);
        ls1 += __shfl_xor_sync(0xffffffffu, ls1, 2);
        lrow0 = lrow0 * scl0 + ls0;
        lrow1 = lrow1 * scl1 + ls1;
        mrow0 = mn0; mrow1 = mn1;
#pragma unroll
        for (int nb = 0; nb < 8; nb++) {
            oc[nb][0] *= scl0; oc[nb][1] *= scl0;
            oc[nb][2] *= scl1; oc[nb][3] *= scl1;
        }

        // repack P into plain-fp16 A-fragments (1-pass PV)
        uint32_t ap[4][4];
#pragma unroll
        for (int ks = 0; ks < 4; ks++) {
            ap[ks][0] = pack_h2(sc[2 * ks][0],     sc[2 * ks][1]);
            ap[ks][1] = pack_h2(sc[2 * ks][2],     sc[2 * ks][3]);
            ap[ks][2] = pack_h2(sc[2 * ks + 1][0], sc[2 * ks + 1][1]);
            ap[ks][3] = pack_h2(sc[2 * ks + 1][2], sc[2 * ks + 1][3]);
        }

        // O += P V : single pass
#pragma unroll
        for (int ks = 0; ks < 4; ks++) {
            uint32_t vh[4][4];
#pragma unroll
            for (int dbp = 0; dbp < 4; dbp++) {
                const uint32_t off = toff128(16 * ks + (lane & 15), dbp * 2 + (lane >> 4));
                ldm_x4_t(vh[dbp], bV + off);
            }
#pragma unroll
            for (int dbp = 0; dbp < 4; dbp++) {
                mma16816h(oc[2 * dbp],     ap[ks], vh[dbp][0], vh[dbp][1]);
                mma16816h(oc[2 * dbp + 1], ap[ks], vh[dbp][2], vh[dbp][3]);
            }
        }
        __syncthreads();
    }

    // epilogue: ctx = O / l -> fp16 split
    const float inv0 = 1.f / lrow0, inv1 = 1.f / lrow1;
    const size_t r0 = rowQ0 + 16 * w + (lane >> 2);
#pragma unroll
    for (int nb = 0; nb < 8; nb++) {
        const int col = hoff + 8 * nb + 2 * (lane & 3);
        uint32_t hw, lw;
        split2h(oc[nb][0] * inv0, oc[nb][1] * inv0, hw, lw);
        *(uint32_t*)&Chi[r0 * E_ + col] = hw;
        *(uint32_t*)&Clo[r0 * E_ + col] = lw;
        split2h(oc[nb][2] * inv1, oc[nb][3] * inv1, hw, lw);
        *(uint32_t*)&Chi[(r0 + 8) * E_ + col] = hw;
        *(uint32_t*)&Clo[(r0 + 8) * E_ + col] = lw;
    }
}

// ---------------------------------------------------------------------------
extern "C" void kernel_launch(void* const* d_in, const int* in_sizes, int n_in,
                              void* d_out, int out_size)
{
    const float* X  = (const float*)d_in[0];
    const float* Wq = (const float*)d_in[1];
    const float* bq = (const float*)d_in[2];
    const float* Wk = (const float*)d_in[3];
    const float* bk = (const float*)d_in[4];
    const float* Wv = (const float*)d_in[5];
    const float* bv = (const float*)d_in[6];
    const float* Wo = (const float*)d_in[7];
    const float* bo = (const float*)d_in[8];
    float* out = (float*)d_out;

    __half *Ahi, *Alo, *WhiB, *WloB, *Qhi, *Qlo, *Khi, *Klo, *Vp;
    cudaGetSymbolAddress((void**)&Ahi, g_Ahi);
    cudaGetSymbolAddress((void**)&Alo, g_Alo);
    cudaGetSymbolAddress((void**)&WhiB, g_Whi);
    cudaGetSymbolAddress((void**)&WloB, g_Wlo);
    cudaGetSymbolAddress((void**)&Qhi, g_Qhi);
    cudaGetSymbolAddress((void**)&Qlo, g_Qlo);
    cudaGetSymbolAddress((void**)&Khi, g_Khi);
    cudaGetSymbolAddress((void**)&Klo, g_Klo);
    cudaGetSymbolAddress((void**)&Vp, g_V);
    const size_t WSZ = (size_t)E_ * E_;

    cudaFuncSetAttribute(gemm_tc, cudaFuncAttributeMaxDynamicSharedMemorySize, SMEM_GEMM);
    cudaFuncSetAttribute(attn_tc, cudaFuncAttributeMaxDynamicSharedMemorySize, SMEM_ATTN);

    const int nX4 = (M_ * E_) / 4;
    const int nW4 = (E_ * E_) / 4;

    SplitJobs sj;
    sj.src[0] = Wq; sj.src[1] = Wk; sj.src[2] = Wv; sj.src[3] = Wo;
    for (int i = 0; i < 4; i++) { sj.hi[i] = WhiB + i * WSZ; sj.lo[i] = WloB + i * WSZ; }
    split_weights<<<dim3((nW4 + 255) / 256, 4), 256>>>(sj, nW4);
    split_fp32<<<(nX4 + 255) / 256, 256>>>(X, Ahi, Alo, nX4);

    // batched Q,K,V projections. Q carries SCALING*log2(e) so attention
    // softmax runs in the exp2 domain (exp2(s~-m~) == exp(s-m)).
    GemmJobs qkv;
    qkv.Whi[0] = WhiB;           qkv.Wlo[0] = WloB;
    qkv.Whi[1] = WhiB + WSZ;     qkv.Wlo[1] = WloB + WSZ;
    qkv.Whi[2] = WhiB + 2 * WSZ; qkv.Wlo[2] = WloB + 2 * WSZ;
    qkv.bias[0] = bq; qkv.bias[1] = bk; qkv.bias[2] = bv;
    qkv.Ohi[0] = Qhi; qkv.Olo[0] = Qlo;
    qkv.Ohi[1] = Khi; qkv.Olo[1] = Klo;
    qkv.Ohi[2] = Vp;  qkv.Olo[2] = nullptr;
    qkv.C[0] = qkv.C[1] = qkv.C[2] = nullptr;
    qkv.alpha[0] = SCALING * LOG2E; qkv.alpha[1] = 1.f; qkv.alpha[2] = 1.f;
    qkv.nt[0] = 3; qkv.nt[1] = 3; qkv.nt[2] = 2;
    gemm_tc<<<dim3(E_ / 128, M_ / 128, 3), 256, SMEM_GEMM>>>(Ahi, Alo, qkv);

    dim3 ag(T_ / 64, B_ * H_);
    attn_tc<<<ag, 128, SMEM_ATTN>>>(Qhi, Qlo, Khi, Klo, Vp, Ahi, Alo);

    // output projection (2-pass, fp32 out)
    GemmJobs oj;
    oj.Whi[0] = WhiB + 3 * WSZ; oj.Wlo[0] = WloB + 3 * WSZ;
    oj.bias[0] = bo;
    oj.Ohi[0] = nullptr; oj.Olo[0] = nullptr;
    oj.C[0] = out;
    oj.alpha[0] = 1.f;
    oj.nt[0] = 2;
    oj.Whi[1] = oj.Whi[2] = nullptr; oj.Wlo[1] = oj.Wlo[2] = nullptr;
    oj.bias[1] = oj.bias[2] = nullptr;
    oj.Ohi[1] = oj.Ohi[2] = nullptr; oj.Olo[1] = oj.Olo[2] = nullptr;
    oj.C[1] = oj.C[2] = nullptr;
    oj.alpha[1] = oj.alpha[2] = 0.f;
    oj.nt[1] = oj.nt[2] = 2;
    gemm_tc<<<dim3(E_ / 128, M_ / 128, 1), 256, SMEM_GEMM>>>(Ahi, Alo, oj);
}